// round 1
// baseline (speedup 1.0000x reference)
#include <cuda_runtime.h>
#include <cstdint>
#include <cstddef>

#define NN   200000
#define EE   800000
#define FIN  128
#define GG   8000

// ---------------- device scratch (no allocations allowed) ----------------
__device__ float g_bufA[(size_t)NN * 128];
__device__ float g_bufB[(size_t)NN * 128];
__device__ float g_bufC[(size_t)NN * 128];
__device__ float g_dis[NN];
__device__ int   g_cnt[NN];
__device__ int   g_gptr[GG + 1];
__device__ int   g_ei64;   // 1 if edge_index is int64, 0 if int32
__device__ int   g_b64;    // 1 if batch is int64, 0 if int32

__device__ __forceinline__ long long ld_idx(const void* p, long long i, int is64) {
    if (is64) return ((const long long*)p)[i];
    return (long long)((const int*)p)[i];
}

// ---------------- dtype width detection (int64 vs int32) ----------------
__global__ void detect_kernel(const void* ei, const void* batch) {
    if (threadIdx.x == 0 && blockIdx.x == 0) {
        const long long* p = (const long long*)ei;
        int ok = 1;
        for (int i = 0; i < 32; i++) { long long v = p[i]; if (v < 0 || v >= NN) ok = 0; }
        g_ei64 = ok;
        const long long* q = (const long long*)batch;
        int ok2 = 1;
        for (int i = 0; i < 32; i++) { long long v = q[i]; if (v < 0 || v >= GG) ok2 = 0; }
        g_b64 = ok2;
    }
}

// ---------------- zeroing ----------------
__global__ void zero_kernel(float* __restrict__ p, long long n4) {
    long long i = (long long)blockIdx.x * blockDim.x + threadIdx.x;
    if (i < n4) ((float4*)p)[i] = make_float4(0.f, 0.f, 0.f, 0.f);
}

__global__ void zero_cnt_kernel() {
    int i = blockIdx.x * blockDim.x + threadIdx.x;
    if (i < NN) g_cnt[i] = 0;
}

// ---------------- degree + inv-sqrt ----------------
__global__ void count_kernel(const void* __restrict__ ei) {
    int i = blockIdx.x * blockDim.x + threadIdx.x;
    if (i >= EE) return;
    int is64 = g_ei64;
    int dst = (int)ld_idx(ei, (long long)EE + i, is64);
    atomicAdd(&g_cnt[dst], 1);
}

__global__ void dis_kernel() {
    int i = blockIdx.x * blockDim.x + threadIdx.x;
    if (i < NN) g_dis[i] = rsqrtf(1.0f + (float)g_cnt[i]);
}

// ---------------- graph boundary pointers (batch is sorted) ----------------
__global__ void gptr_kernel(const void* __restrict__ batch) {
    int i = blockIdx.x * blockDim.x + threadIdx.x;
    if (i >= NN) return;
    int is64 = g_b64;
    int bi = (int)ld_idx(batch, i, is64);
    if (i == 0) {
        for (int g = 0; g <= bi; g++) g_gptr[g] = 0;
    } else {
        int bp = (int)ld_idx(batch, i - 1, is64);
        for (int g = bp + 1; g <= bi; g++) g_gptr[g] = i;
    }
    if (i == NN - 1) {
        for (int g = bi + 1; g <= GG; g++) g_gptr[g] = NN;
    }
}

// ---------------- instance norm (block per graph, thread per channel) -----
__global__ void instnorm_kernel(const float* __restrict__ x,
                                const float* __restrict__ wp,
                                const float* __restrict__ bp) {
    int g = blockIdx.x;
    int c = threadIdx.x;           // 128 threads
    int s = g_gptr[g], e = g_gptr[g + 1];
    if (s >= e) return;
    float w = wp[0], b = bp[0];
    float sum = 0.f, sq = 0.f;
    for (int i = s; i < e; i++) {
        float v = x[(size_t)i * FIN + c];
        sum += v; sq += v * v;
    }
    float cnt  = (float)(e - s);
    float mean = sum / cnt;
    float var  = sq / cnt - mean * mean;
    float inv  = rsqrtf(var + 1e-5f);
    for (int i = s; i < e; i++) {
        float v = x[(size_t)i * FIN + c];
        g_bufA[(size_t)i * FIN + c] = (v - mean) * inv * w + b;
    }
}

// ---------------- dense per-node GEMM: Y[N,COUT] = X[N,CIN] @ W ----------
template<int CIN, int COUT>
__global__ __launch_bounds__(256)
void gemm_kernel(const float* __restrict__ X, const float* __restrict__ W,
                 float* __restrict__ Y) {
    constexpr int TPN = COUT / 4;        // threads per node group
    constexpr int NG  = 256 / TPN;       // node groups per block
    constexpr int NB  = NG * 2;          // nodes per block (2 nodes / thread)
    __shared__ __align__(16) float sW[CIN * COUT];
    __shared__ float sX[NB * CIN];

    int tid = threadIdx.x;
    for (int idx = tid; idx < CIN * COUT; idx += 256) sW[idx] = W[idx];
    long long n0 = (long long)blockIdx.x * NB;
    for (int idx = tid; idx < NB * CIN; idx += 256) {
        long long node = n0 + idx / CIN;
        sX[idx] = (node < NN) ? X[node * CIN + (idx % CIN)] : 0.f;
    }
    __syncthreads();

    int grp = tid / TPN;
    int col = (tid % TPN) * 4;
    const float* x0 = &sX[(grp * 2 + 0) * CIN];
    const float* x1 = &sX[(grp * 2 + 1) * CIN];
    float a00 = 0, a01 = 0, a02 = 0, a03 = 0;
    float a10 = 0, a11 = 0, a12 = 0, a13 = 0;
#pragma unroll 16
    for (int k = 0; k < CIN; k++) {
        float4 w4 = *(const float4*)&sW[k * COUT + col];
        float xa = x0[k], xb = x1[k];
        a00 += xa * w4.x; a01 += xa * w4.y; a02 += xa * w4.z; a03 += xa * w4.w;
        a10 += xb * w4.x; a11 += xb * w4.y; a12 += xb * w4.z; a13 += xb * w4.w;
    }
    long long na = n0 + grp * 2, nb = na + 1;
    if (na < NN) *(float4*)&Y[na * COUT + col] = make_float4(a00, a01, a02, a03);
    if (nb < NN) *(float4*)&Y[nb * COUT + col] = make_float4(a10, a11, a12, a13);
}

// ---------------- edge scatter: ACC[dst] += H[src] * dis[src] ------------
template<int C>
__global__ void scatter_kernel(const float* __restrict__ H,
                               float* __restrict__ ACC,
                               const void* __restrict__ ei) {
    long long t = (long long)blockIdx.x * blockDim.x + threadIdx.x;
    long long eid = t >> 5;
    int lane = (int)(t & 31);
    if (eid >= EE) return;
    int is64 = g_ei64;
    int src = (int)ld_idx(ei, eid, is64);
    int dst = (int)ld_idx(ei, (long long)EE + eid, is64);
    float ds = g_dis[src];
    const float* hrow = &H[(size_t)src * C];
    float* arow = &ACC[(size_t)dst * C];
#pragma unroll
    for (int c = lane; c < C; c += 32)
        atomicAdd(&arow[c], hrow[c] * ds);
}

// ---------------- finalize: relu(dis_i*acc + h_i*dis_i^2 + b) (in place) --
template<int C>
__global__ void finalize_kernel(const float* __restrict__ H,
                                float* __restrict__ ACC,
                                const float* __restrict__ bias) {
    long long idx = (long long)blockIdx.x * blockDim.x + threadIdx.x;
    if (idx >= (long long)NN * C) return;
    int i = (int)(idx / C);
    int c = (int)(idx % C);
    float d = g_dis[i];
    float v = d * ACC[idx] + H[idx] * d * d + bias[c];
    ACC[idx] = fmaxf(v, 0.f);
}

// ---------------- fused head: max-pool -> lin1+relu -> lin2 --------------
__global__ __launch_bounds__(256)
void head_kernel(const float* __restrict__ H3,
                 const float* __restrict__ l1W, const float* __restrict__ l1b,
                 const float* __restrict__ l2W, const float* __restrict__ l2b,
                 float* __restrict__ out) {
    __shared__ float sp[128];
    __shared__ float st[256];
    int g = blockIdx.x;
    int tid = threadIdx.x;
    int s = g_gptr[g], e = g_gptr[g + 1];
    if (tid < 128) {
        float m = 0.f;                       // relu output >= 0; empty graph -> 0
        for (int i = s; i < e; i++)
            m = fmaxf(m, H3[(size_t)i * 128 + tid]);
        sp[tid] = m;
    }
    __syncthreads();
    {
        float sum = l1b[tid];
#pragma unroll 16
        for (int k = 0; k < 128; k++) sum += sp[k] * l1W[k * 256 + tid];
        st[tid] = fmaxf(sum, 0.f);
    }
    __syncthreads();
    if (tid < 128) {
        float sum = l2b[tid];
#pragma unroll 16
        for (int k = 0; k < 256; k++) sum += st[k] * l2W[k * 128 + tid];
        out[(size_t)g * 128 + tid] = sum;
    }
}

// ---------------- launch ----------------
extern "C" void kernel_launch(void* const* d_in, const int* in_sizes, int n_in,
                              void* d_out, int out_size) {
    const float* x     = (const float*)d_in[0];
    const void*  ei    = d_in[1];
    const void*  batch = d_in[2];
    const float* nw    = (const float*)d_in[3];
    const float* nbi   = (const float*)d_in[4];
    const float* W1    = (const float*)d_in[5];
    const float* b1    = (const float*)d_in[6];
    const float* W2    = (const float*)d_in[7];
    const float* b2    = (const float*)d_in[8];
    const float* W3    = (const float*)d_in[9];
    const float* b3    = (const float*)d_in[10];
    const float* l1W   = (const float*)d_in[11];
    const float* l1b   = (const float*)d_in[12];
    const float* l2W   = (const float*)d_in[13];
    const float* l2b   = (const float*)d_in[14];
    float* out = (float*)d_out;

    void *pA, *pB, *pC;
    cudaGetSymbolAddress(&pA, g_bufA);
    cudaGetSymbolAddress(&pB, g_bufB);
    cudaGetSymbolAddress(&pC, g_bufC);
    float* fA = (float*)pA;
    float* fB = (float*)pB;
    float* fC = (float*)pC;

    detect_kernel<<<1, 1>>>(ei, batch);

    // degrees + dis
    zero_cnt_kernel<<<(NN + 255) / 256, 256>>>();
    count_kernel<<<(EE + 255) / 256, 256>>>(ei);
    dis_kernel<<<(NN + 255) / 256, 256>>>();

    // graph boundaries
    gptr_kernel<<<(NN + 255) / 256, 256>>>(batch);

    // instance norm -> A (128 ch)
    instnorm_kernel<<<GG, 128>>>(x, nw, nbi);

    // layer 1: A(128) @ W1 -> B(32); scatter -> C; finalize -> C
    gemm_kernel<128, 32><<<(NN + 63) / 64, 256>>>(fA, W1, fB);
    zero_kernel<<<(int)(((long long)NN * 32 / 4 + 255) / 256), 256>>>(fC, (long long)NN * 32 / 4);
    scatter_kernel<32><<<(int)(((long long)EE * 32 + 255) / 256), 256>>>(fB, fC, ei);
    finalize_kernel<32><<<(int)(((long long)NN * 32 + 255) / 256), 256>>>(fB, fC, b1);

    // layer 2: C(32) @ W2 -> B(64); scatter -> A; finalize -> A
    gemm_kernel<32, 64><<<(NN + 31) / 32, 256>>>(fC, W2, fB);
    zero_kernel<<<(int)(((long long)NN * 64 / 4 + 255) / 256), 256>>>(fA, (long long)NN * 64 / 4);
    scatter_kernel<64><<<(int)(((long long)EE * 32 + 255) / 256), 256>>>(fB, fA, ei);
    finalize_kernel<64><<<(int)(((long long)NN * 64 + 255) / 256), 256>>>(fB, fA, b2);

    // layer 3: A(64) @ W3 -> B(128); scatter -> C; finalize -> C
    gemm_kernel<64, 128><<<(NN + 15) / 16, 256>>>(fA, W3, fB);
    zero_kernel<<<(int)(((long long)NN * 128 / 4 + 255) / 256), 256>>>(fC, (long long)NN * 128 / 4);
    scatter_kernel<128><<<(int)(((long long)EE * 32 + 255) / 256), 256>>>(fB, fC, ei);
    finalize_kernel<128><<<(int)(((long long)NN * 128 + 255) / 256), 256>>>(fB, fC, b3);

    // fused pool + MLP head
    head_kernel<<<GG, 256>>>(fC, l1W, l1b, l2W, l2b, out);
}

// round 2
// speedup vs baseline: 1.2267x; 1.2267x over previous
#include <cuda_runtime.h>
#include <cstdint>
#include <cstddef>

#define NN   200000
#define EE   800000
#define FIN  128
#define GG   8000
#define SCAN_B 512

// ---------------- device scratch ----------------
__device__ float g_bufA[(size_t)NN * 128];
__device__ float g_bufB[(size_t)NN * 128];
__device__ float g_bufC[(size_t)NN * 128];
__device__ float g_dis[NN];
__device__ int   g_cnt[NN];
__device__ int   g_rowptr[NN + 1];
__device__ int   g_fill[NN];
__device__ int   g_csr_src[EE];
__device__ float g_csr_w[EE];
__device__ int   g_bsum[SCAN_B];
__device__ int   g_boff[SCAN_B];
__device__ int   g_gptr[GG + 1];
__device__ int   g_nodeg[NN];
__device__ float g_na[GG * 128];
__device__ float g_nb[GG * 128];
__device__ int   g_pool[GG * 128];      // float bits, post-relu (>=0) so int max == float max
__device__ int   g_ei64;
__device__ int   g_b64;

__device__ __forceinline__ long long ld_idx(const void* p, long long i, int is64) {
    if (is64) return ((const long long*)p)[i];
    return (long long)((const int*)p)[i];
}

// ---------------- dtype width detection ----------------
__global__ void detect_kernel(const void* ei, const void* batch) {
    if (threadIdx.x == 0 && blockIdx.x == 0) {
        const long long* p = (const long long*)ei;
        int ok = 1;
        for (int i = 0; i < 32; i++) { long long v = p[i]; if (v < 0 || v >= NN) ok = 0; }
        g_ei64 = ok;
        const long long* q = (const long long*)batch;
        int ok2 = 1;
        for (int i = 0; i < 32; i++) { long long v = q[i]; if (v < 0 || v >= GG) ok2 = 0; }
        g_b64 = ok2;
    }
}

// ---------------- small init kernels ----------------
__global__ void zero_cnt_kernel() {
    int i = blockIdx.x * blockDim.x + threadIdx.x;
    if (i < NN) g_cnt[i] = 0;
}
__global__ void zero_pool_kernel() {
    int i = blockIdx.x * blockDim.x + threadIdx.x;
    if (i < GG * 128) g_pool[i] = 0;
}
__global__ void nodeg_kernel(const void* __restrict__ batch) {
    int i = blockIdx.x * blockDim.x + threadIdx.x;
    if (i < NN) g_nodeg[i] = (int)ld_idx(batch, i, g_b64);
}

// ---------------- degree + inv-sqrt ----------------
__global__ void count_kernel(const void* __restrict__ ei) {
    int i = blockIdx.x * blockDim.x + threadIdx.x;
    if (i >= EE) return;
    int dst = (int)ld_idx(ei, (long long)EE + i, g_ei64);
    atomicAdd(&g_cnt[dst], 1);
}
__global__ void dis_kernel() {
    int i = blockIdx.x * blockDim.x + threadIdx.x;
    if (i < NN) g_dis[i] = rsqrtf(1.0f + (float)g_cnt[i]);
}

// ---------------- exclusive scan of g_cnt -> g_rowptr ----------------
__global__ void scan1_kernel() {
    __shared__ int s[SCAN_B];
    int tid = threadIdx.x;
    int i = blockIdx.x * SCAN_B + tid;
    int v = (i < NN) ? g_cnt[i] : 0;
    s[tid] = v;
    __syncthreads();
    for (int off = 1; off < SCAN_B; off <<= 1) {
        int t = (tid >= off) ? s[tid - off] : 0;
        __syncthreads();
        s[tid] += t;
        __syncthreads();
    }
    if (i < NN) g_rowptr[i] = s[tid] - v;
    if (tid == SCAN_B - 1) g_bsum[blockIdx.x] = s[tid];
}
__global__ void scan2_kernel(int nb) {
    __shared__ int s[SCAN_B];
    int tid = threadIdx.x;
    int v = (tid < nb) ? g_bsum[tid] : 0;
    s[tid] = v;
    __syncthreads();
    for (int off = 1; off < SCAN_B; off <<= 1) {
        int t = (tid >= off) ? s[tid - off] : 0;
        __syncthreads();
        s[tid] += t;
        __syncthreads();
    }
    g_boff[tid] = s[tid] - v;
}
__global__ void scan3_kernel() {
    int i = blockIdx.x * blockDim.x + threadIdx.x;
    if (i < NN) {
        int v = g_rowptr[i] + g_boff[i / SCAN_B];
        g_rowptr[i] = v;
        g_fill[i] = v;
    }
    if (i == 0) g_rowptr[NN] = EE;
}

// ---------------- CSR fill ----------------
__global__ void fill_kernel(const void* __restrict__ ei) {
    int i = blockIdx.x * blockDim.x + threadIdx.x;
    if (i >= EE) return;
    int is64 = g_ei64;
    int src = (int)ld_idx(ei, i, is64);
    int dst = (int)ld_idx(ei, (long long)EE + i, is64);
    int pos = atomicAdd(&g_fill[dst], 1);
    g_csr_src[pos] = src;
    g_csr_w[pos] = g_dis[src];
}

// ---------------- graph boundary pointers (batch sorted) ----------------
__global__ void gptr_kernel(const void* __restrict__ batch) {
    int i = blockIdx.x * blockDim.x + threadIdx.x;
    if (i >= NN) return;
    int is64 = g_b64;
    int bi = (int)ld_idx(batch, i, is64);
    if (i == 0) {
        for (int g = 0; g <= bi; g++) g_gptr[g] = 0;
    } else {
        int bp = (int)ld_idx(batch, i - 1, is64);
        for (int g = bp + 1; g <= bi; g++) g_gptr[g] = i;
    }
    if (i == NN - 1) {
        for (int g = bi + 1; g <= GG; g++) g_gptr[g] = NN;
    }
}

// ---------------- instance norm stats -> affine (v*na + nb) --------------
__global__ void stats_kernel(const float* __restrict__ x,
                             const float* __restrict__ wp,
                             const float* __restrict__ bp) {
    int g = blockIdx.x;
    int c = threadIdx.x;   // 128
    int s = g_gptr[g], e = g_gptr[g + 1];
    if (s >= e) { g_na[g * 128 + c] = 0.f; g_nb[g * 128 + c] = 0.f; return; }
    float w = wp[0], b = bp[0];
    float sum = 0.f, sq = 0.f;
    for (int i = s; i < e; i++) {
        float v = x[(size_t)i * FIN + c];
        sum += v; sq += v * v;
    }
    float cnt  = (float)(e - s);
    float mean = sum / cnt;
    float var  = sq / cnt - mean * mean;
    float inv  = rsqrtf(var + 1e-5f);
    float na = inv * w;
    g_na[g * 128 + c] = na;
    g_nb[g * 128 + c] = b - mean * na;
}

// ---------------- node GEMM: Y[N,COUT] = X[N,CIN] @ W -------------------
// NORM: apply per-graph instance-norm affine on load (CIN must be 128).
// EPI: 0 = plain store, 1 = bias+relu store, 2 = bias+relu atomicMax into g_pool.
template<int CIN, int COUT, bool NORM, int EPI>
__global__ __launch_bounds__(256)
void gemm_kernel(const float* __restrict__ X, const float* __restrict__ W,
                 const float* __restrict__ bias, float* __restrict__ Y) {
    constexpr int TPN = COUT / 4;
    constexpr int NG  = 256 / TPN;
    constexpr int NB  = NG * 2;
    __shared__ __align__(16) float sW[CIN * COUT];
    __shared__ float sX[NB * CIN];

    int tid = threadIdx.x;
    for (int idx = tid; idx < CIN * COUT; idx += 256) sW[idx] = W[idx];
    long long n0 = (long long)blockIdx.x * NB;
    for (int idx = tid; idx < NB * CIN; idx += 256) {
        long long node = n0 + idx / CIN;
        float v = 0.f;
        if (node < NN) {
            v = X[node * CIN + (idx % CIN)];
            if (NORM) {
                int g = g_nodeg[node];
                int c = idx % CIN;
                v = v * g_na[g * 128 + c] + g_nb[g * 128 + c];
            }
        }
        sX[idx] = v;
    }
    __syncthreads();

    int grp = tid / TPN;
    int col = (tid % TPN) * 4;
    const float* x0 = &sX[(grp * 2 + 0) * CIN];
    const float* x1 = &sX[(grp * 2 + 1) * CIN];
    float a00 = 0, a01 = 0, a02 = 0, a03 = 0;
    float a10 = 0, a11 = 0, a12 = 0, a13 = 0;
#pragma unroll 16
    for (int k = 0; k < CIN; k++) {
        float4 w4 = *(const float4*)&sW[k * COUT + col];
        float xa = x0[k], xb = x1[k];
        a00 += xa * w4.x; a01 += xa * w4.y; a02 += xa * w4.z; a03 += xa * w4.w;
        a10 += xb * w4.x; a11 += xb * w4.y; a12 += xb * w4.z; a13 += xb * w4.w;
    }

    long long na_ = n0 + grp * 2, nb_ = na_ + 1;
    if (EPI == 0) {
        if (na_ < NN) *(float4*)&Y[na_ * COUT + col] = make_float4(a00, a01, a02, a03);
        if (nb_ < NN) *(float4*)&Y[nb_ * COUT + col] = make_float4(a10, a11, a12, a13);
    } else {
        float b0 = bias[col], b1v = bias[col + 1], b2v = bias[col + 2], b3v = bias[col + 3];
        a00 = fmaxf(a00 + b0, 0.f); a01 = fmaxf(a01 + b1v, 0.f);
        a02 = fmaxf(a02 + b2v, 0.f); a03 = fmaxf(a03 + b3v, 0.f);
        a10 = fmaxf(a10 + b0, 0.f); a11 = fmaxf(a11 + b1v, 0.f);
        a12 = fmaxf(a12 + b2v, 0.f); a13 = fmaxf(a13 + b3v, 0.f);
        if (EPI == 1) {
            if (na_ < NN) *(float4*)&Y[na_ * COUT + col] = make_float4(a00, a01, a02, a03);
            if (nb_ < NN) *(float4*)&Y[nb_ * COUT + col] = make_float4(a10, a11, a12, a13);
        } else {
            if (na_ < NN) {
                int g = g_nodeg[na_];
                atomicMax(&g_pool[g * 128 + col + 0], __float_as_int(a00));
                atomicMax(&g_pool[g * 128 + col + 1], __float_as_int(a01));
                atomicMax(&g_pool[g * 128 + col + 2], __float_as_int(a02));
                atomicMax(&g_pool[g * 128 + col + 3], __float_as_int(a03));
            }
            if (nb_ < NN) {
                int g = g_nodeg[nb_];
                atomicMax(&g_pool[g * 128 + col + 0], __float_as_int(a10));
                atomicMax(&g_pool[g * 128 + col + 1], __float_as_int(a11));
                atomicMax(&g_pool[g * 128 + col + 2], __float_as_int(a12));
                atomicMax(&g_pool[g * 128 + col + 3], __float_as_int(a13));
            }
        }
    }
}

// ---------------- CSR gather: O = P @ H (optional bias+relu) ------------
// O_i = dis_i * sum_{e in row i} H[src_e]*dis[src_e]  +  H_i*dis_i^2  (+b, relu)
template<int C, bool EPI>
__global__ __launch_bounds__(256)
void gather_kernel(const float* __restrict__ H, float* __restrict__ O,
                   const float* __restrict__ bias) {
    constexpr int NPB = 256 / C;
    int node = blockIdx.x * NPB + threadIdx.x / C;
    int lane = threadIdx.x % C;
    if (node >= NN) return;
    int s = g_rowptr[node], e = g_rowptr[node + 1];
    float acc = 0.f;
    for (int k = s; k < e; k++) {
        int src = g_csr_src[k];
        float w = g_csr_w[k];
        acc += H[(size_t)src * C + lane] * w;
    }
    float d = g_dis[node];
    float h = H[(size_t)node * C + lane];
    float v = d * acc + h * d * d;
    if (EPI) v = fmaxf(v + bias[lane], 0.f);
    O[(size_t)node * C + lane] = v;
}

// ---------------- head GEMMs (weight-stationary, graph-looping) ---------
// Y[g, col0+c] = act( sum_k X[g,k]*W[k, col0+c] + b[col0+c] )
template<int CIN, int CTILE, bool RELU>
__global__ __launch_bounds__(256)
void hgemm_kernel(const float* __restrict__ X, const float* __restrict__ W,
                  int ldW, const float* __restrict__ bias,
                  float* __restrict__ Y, int ldY, int gchunks) {
    constexpr int GPB = 256 / CTILE;
    __shared__ float sW[CIN * CTILE];
    __shared__ float sX[GPB * CIN];
    int tid = threadIdx.x;
    int col0 = blockIdx.y * CTILE;
    for (int idx = tid; idx < CIN * CTILE; idx += 256)
        sW[idx] = W[(idx / CTILE) * ldW + col0 + (idx % CTILE)];

    int per = (GG + gchunks - 1) / gchunks;
    int gstart = blockIdx.x * per;
    int gend = min(gstart + per, GG);
    __syncthreads();

    for (int g0 = gstart; g0 < gend; g0 += GPB) {
        for (int idx = tid; idx < GPB * CIN; idx += 256) {
            int g = g0 + idx / CIN;
            sX[idx] = (g < GG) ? X[(size_t)g * CIN + (idx % CIN)] : 0.f;
        }
        __syncthreads();
        int lg = tid / CTILE;
        int c = tid % CTILE;
        float acc = bias[col0 + c];
        const float* xr = &sX[lg * CIN];
#pragma unroll 16
        for (int k = 0; k < CIN; k++) acc += xr[k] * sW[k * CTILE + c];
        if (RELU) acc = fmaxf(acc, 0.f);
        int g = g0 + lg;
        if (g < GG) Y[(size_t)g * ldY + col0 + c] = acc;
        __syncthreads();
    }
}

// ---------------- launch ----------------
extern "C" void kernel_launch(void* const* d_in, const int* in_sizes, int n_in,
                              void* d_out, int out_size) {
    const float* x     = (const float*)d_in[0];
    const void*  ei    = d_in[1];
    const void*  batch = d_in[2];
    const float* nw    = (const float*)d_in[3];
    const float* nbi   = (const float*)d_in[4];
    const float* W1    = (const float*)d_in[5];
    const float* b1    = (const float*)d_in[6];
    const float* W2    = (const float*)d_in[7];
    const float* b2    = (const float*)d_in[8];
    const float* W3    = (const float*)d_in[9];
    const float* b3    = (const float*)d_in[10];
    const float* l1W   = (const float*)d_in[11];
    const float* l1b   = (const float*)d_in[12];
    const float* l2W   = (const float*)d_in[13];
    const float* l2b   = (const float*)d_in[14];
    float* out = (float*)d_out;

    void *pA, *pB, *pC, *pPool;
    cudaGetSymbolAddress(&pA, g_bufA);
    cudaGetSymbolAddress(&pB, g_bufB);
    cudaGetSymbolAddress(&pC, g_bufC);
    cudaGetSymbolAddress(&pPool, g_pool);
    float* fA = (float*)pA;
    float* fB = (float*)pB;
    float* fC = (float*)pC;
    const float* poolf = (const float*)pPool;

    const int NB_SCAN = (NN + SCAN_B - 1) / SCAN_B;   // 391

    detect_kernel<<<1, 1>>>(ei, batch);
    nodeg_kernel<<<(NN + 255) / 256, 256>>>(batch);
    zero_cnt_kernel<<<(NN + 255) / 256, 256>>>();
    zero_pool_kernel<<<(GG * 128 + 255) / 256, 256>>>();
    count_kernel<<<(EE + 255) / 256, 256>>>(ei);
    dis_kernel<<<(NN + 255) / 256, 256>>>();

    // CSR by destination
    scan1_kernel<<<NB_SCAN, SCAN_B>>>();
    scan2_kernel<<<1, SCAN_B>>>(NB_SCAN);
    scan3_kernel<<<(NN + 255) / 256, 256>>>();
    fill_kernel<<<(EE + 255) / 256, 256>>>(ei);

    // instance norm affine
    gptr_kernel<<<(NN + 255) / 256, 256>>>(batch);
    stats_kernel<<<GG, 128>>>(x, nw, nbi);

    // layer 1: GEMM first (narrow out) with fused norm, then propagate w/ bias+relu
    gemm_kernel<128, 32, true, 0><<<(NN + 63) / 64, 256>>>(x, W1, nullptr, fB);
    gather_kernel<32, true><<<(NN * 32 + 255) / 256, 256>>>(fB, fA, b1);

    // layer 2: propagate first (narrow in: 32ch), then GEMM w/ bias+relu
    gather_kernel<32, false><<<(NN * 32 + 255) / 256, 256>>>(fA, fC, nullptr);
    gemm_kernel<32, 64, false, 1><<<(NN + 31) / 32, 256>>>(fC, W2, b2, fB);

    // layer 3: propagate first (64ch), then GEMM w/ bias+relu + fused max-pool
    gather_kernel<64, false><<<(NN * 64 + 255) / 256, 256>>>(fB, fC, nullptr);
    gemm_kernel<64, 128, false, 2><<<(NN + 15) / 16, 256>>>(fC, W3, b3, nullptr);

    // head: pooled[G,128] @ l1W -> relu -> T[G,256] @ l2W -> out[G,128]
    {
        dim3 grid1(32, 4);   // 256/64 col tiles
        hgemm_kernel<128, 64, true><<<grid1, 256>>>(poolf, l1W, 256, l1b, fB, 256, 32);
        dim3 grid2(32, 4);   // 128/32 col tiles
        hgemm_kernel<256, 32, false><<<grid2, 256>>>(fB, l2W, 128, l2b, out, 128, 32);
    }
}

// round 3
// speedup vs baseline: 2.2161x; 1.8066x over previous
#include <cuda_runtime.h>
#include <cstdint>
#include <cstddef>

#define NN   200000
#define EE   800000
#define FIN  128
#define GG   8000
#define SCAN_B 512

// ---------------- device scratch ----------------
__device__ float g_bufA[(size_t)NN * 128];
__device__ float g_bufB[(size_t)NN * 128];
__device__ float g_bufC[(size_t)NN * 128];
__device__ float g_dis[NN];
__device__ int   g_cnt[NN];
__device__ int   g_rowptr[NN + 1];
__device__ int   g_fill[NN];
__device__ float2 g_csr2[EE];          // packed {src_as_float_bits, dis[src]}
__device__ int   g_bsum[SCAN_B];
__device__ int   g_boff[SCAN_B];
__device__ int   g_gptr[GG + 1];
__device__ int   g_nodeg[NN];
__device__ float g_na[GG * 128];
__device__ float g_nb[GG * 128];
__device__ int   g_pool[GG * 128];     // float bits; values >= 0 so int-max == float-max
__device__ int   g_ei64;
__device__ int   g_b64;

__device__ __forceinline__ long long ld_idx(const void* p, long long i, int is64) {
    if (is64) return ((const long long*)p)[i];
    return (long long)((const int*)p)[i];
}

// ---------------- dtype width detection ----------------
__global__ void detect_kernel(const void* ei, const void* batch) {
    if (threadIdx.x == 0 && blockIdx.x == 0) {
        const long long* p = (const long long*)ei;
        int ok = 1;
        for (int i = 0; i < 32; i++) { long long v = p[i]; if (v < 0 || v >= NN) ok = 0; }
        g_ei64 = ok;
        const long long* q = (const long long*)batch;
        int ok2 = 1;
        for (int i = 0; i < 32; i++) { long long v = q[i]; if (v < 0 || v >= GG) ok2 = 0; }
        g_b64 = ok2;
    }
}

// ---------------- merged init ----------------
__global__ void init_kernel() {
    int i = blockIdx.x * blockDim.x + threadIdx.x;
    if (i < NN) g_cnt[i] = 0;
    if (i < GG * 128) g_pool[i] = 0;
}

// nodeg + graph boundary pointers (batch sorted)
__global__ void batchinfo_kernel(const void* __restrict__ batch) {
    int i = blockIdx.x * blockDim.x + threadIdx.x;
    if (i >= NN) return;
    int is64 = g_b64;
    int bi = (int)ld_idx(batch, i, is64);
    g_nodeg[i] = bi;
    if (i == 0) {
        for (int g = 0; g <= bi; g++) g_gptr[g] = 0;
    } else {
        int bp = (int)ld_idx(batch, i - 1, is64);
        for (int g = bp + 1; g <= bi; g++) g_gptr[g] = i;
    }
    if (i == NN - 1) {
        for (int g = bi + 1; g <= GG; g++) g_gptr[g] = NN;
    }
}

// ---------------- degree + inv-sqrt ----------------
__global__ void count_kernel(const void* __restrict__ ei) {
    int i = blockIdx.x * blockDim.x + threadIdx.x;
    if (i >= EE) return;
    int dst = (int)ld_idx(ei, (long long)EE + i, g_ei64);
    atomicAdd(&g_cnt[dst], 1);
}
__global__ void dis_kernel() {
    int i = blockIdx.x * blockDim.x + threadIdx.x;
    if (i < NN) g_dis[i] = rsqrtf(1.0f + (float)g_cnt[i]);
}

// ---------------- exclusive scan of g_cnt -> g_rowptr ----------------
__global__ void scan1_kernel() {
    __shared__ int s[SCAN_B];
    int tid = threadIdx.x;
    int i = blockIdx.x * SCAN_B + tid;
    int v = (i < NN) ? g_cnt[i] : 0;
    s[tid] = v;
    __syncthreads();
    for (int off = 1; off < SCAN_B; off <<= 1) {
        int t = (tid >= off) ? s[tid - off] : 0;
        __syncthreads();
        s[tid] += t;
        __syncthreads();
    }
    if (i < NN) g_rowptr[i] = s[tid] - v;
    if (tid == SCAN_B - 1) g_bsum[blockIdx.x] = s[tid];
}
__global__ void scan2_kernel(int nb) {
    __shared__ int s[SCAN_B];
    int tid = threadIdx.x;
    int v = (tid < nb) ? g_bsum[tid] : 0;
    s[tid] = v;
    __syncthreads();
    for (int off = 1; off < SCAN_B; off <<= 1) {
        int t = (tid >= off) ? s[tid - off] : 0;
        __syncthreads();
        s[tid] += t;
        __syncthreads();
    }
    g_boff[tid] = s[tid] - v;
}
__global__ void scan3_kernel() {
    int i = blockIdx.x * blockDim.x + threadIdx.x;
    if (i < NN) {
        int v = g_rowptr[i] + g_boff[i / SCAN_B];
        g_rowptr[i] = v;
        g_fill[i] = v;
    }
    if (i == 0) g_rowptr[NN] = EE;
}

// ---------------- CSR fill (packed) ----------------
__global__ void fill_kernel(const void* __restrict__ ei) {
    int i = blockIdx.x * blockDim.x + threadIdx.x;
    if (i >= EE) return;
    int is64 = g_ei64;
    int src = (int)ld_idx(ei, i, is64);
    int dst = (int)ld_idx(ei, (long long)EE + i, is64);
    int pos = atomicAdd(&g_fill[dst], 1);
    g_csr2[pos] = make_float2(__int_as_float(src), g_dis[src]);
}

// ---------------- instance norm stats -> affine (v*na + nb) --------------
__global__ void stats_kernel(const float* __restrict__ x,
                             const float* __restrict__ wp,
                             const float* __restrict__ bp) {
    int g = blockIdx.x;
    int c = threadIdx.x;   // 128
    int s = g_gptr[g], e = g_gptr[g + 1];
    if (s >= e) { g_na[g * 128 + c] = 0.f; g_nb[g * 128 + c] = 0.f; return; }
    float w = wp[0], b = bp[0];
    float sum = 0.f, sq = 0.f;
    for (int i = s; i < e; i++) {
        float v = x[(size_t)i * FIN + c];
        sum += v; sq += v * v;
    }
    float cnt  = (float)(e - s);
    float mean = sum / cnt;
    float var  = sq / cnt - mean * mean;
    float inv  = rsqrtf(var + 1e-5f);
    float na = inv * w;
    g_na[g * 128 + c] = na;
    g_nb[g * 128 + c] = b - mean * na;
}

// ---------------- register-tiled GEMM: Y[R,COUT] = X[R,CIN] @ W ----------
// 8x8 thread tile, k-chunks of KC. NORM: fuse per-graph instance-norm affine
// into the X tile load (CIN must be 128). EPI: 0 plain, 1 bias+relu,
// 2 bias+relu+max-pool (NO store), 3 bias only.
template<int CIN, int COUT, int KC, bool NORM, int EPI>
__global__ __launch_bounds__(256, 2)
void tgemm_kernel(const float* __restrict__ X, const float* __restrict__ W,
                  const float* __restrict__ bias, float* __restrict__ Y,
                  int nrows) {
    constexpr int NT = 8;                 // cols per thread
    constexpr int MT = 8;                 // rows per thread
    constexpr int TC = COUT / NT;         // threads along cols
    constexpr int RG = 256 / TC;          // row groups per block
    constexpr int MB = RG * MT;           // rows per block
    constexpr int KQ = KC / 4;

    __shared__ __align__(16) float sXT[KC * MB];   // transposed: [k][row]
    __shared__ __align__(16) float sW[KC * COUT];  // [k][col]

    int tid = threadIdx.x;
    int r0 = blockIdx.x * MB;
    int grp = tid / TC;
    int clo = (tid % TC) * NT;
    int nlo = grp * MT;

    float acc[8][8];
#pragma unroll
    for (int i = 0; i < 8; i++)
#pragma unroll
        for (int j = 0; j < 8; j++) acc[i][j] = 0.f;

    for (int k0 = 0; k0 < CIN; k0 += KC) {
        // load W tile (contiguous rows of W)
        const float4* Wsrc = (const float4*)(W + (size_t)k0 * COUT);
#pragma unroll
        for (int i = tid; i < KC * COUT / 4; i += 256)
            ((float4*)sW)[i] = Wsrc[i];
        // load X tile, transposed
        for (int i = tid; i < MB * KQ; i += 256) {
            int rl = i / KQ;
            int kq = i % KQ;
            int row = r0 + rl;
            float4 v = make_float4(0.f, 0.f, 0.f, 0.f);
            if (row < nrows) {
                v = *(const float4*)&X[(size_t)row * CIN + k0 + kq * 4];
                if (NORM) {
                    int g = g_nodeg[row];
                    const float4 na = *(const float4*)&g_na[g * 128 + k0 + kq * 4];
                    const float4 nb = *(const float4*)&g_nb[g * 128 + k0 + kq * 4];
                    v.x = v.x * na.x + nb.x; v.y = v.y * na.y + nb.y;
                    v.z = v.z * na.z + nb.z; v.w = v.w * na.w + nb.w;
                }
            }
            int kk = kq * 4;
            sXT[(kk + 0) * MB + rl] = v.x;
            sXT[(kk + 1) * MB + rl] = v.y;
            sXT[(kk + 2) * MB + rl] = v.z;
            sXT[(kk + 3) * MB + rl] = v.w;
        }
        __syncthreads();

#pragma unroll
        for (int k = 0; k < KC; k++) {
            float xv[8], wv[8];
            *(float4*)&xv[0] = *(const float4*)&sXT[k * MB + nlo];
            *(float4*)&xv[4] = *(const float4*)&sXT[k * MB + nlo + 4];
            *(float4*)&wv[0] = *(const float4*)&sW[k * COUT + clo];
            *(float4*)&wv[4] = *(const float4*)&sW[k * COUT + clo + 4];
#pragma unroll
            for (int i = 0; i < 8; i++)
#pragma unroll
                for (int j = 0; j < 8; j++)
                    acc[i][j] += xv[i] * wv[j];
        }
        __syncthreads();
    }

    float bv[8];
    if (EPI >= 1) {
        *(float4*)&bv[0] = *(const float4*)&bias[clo];
        *(float4*)&bv[4] = *(const float4*)&bias[clo + 4];
    }

    if (EPI == 2) {
        // bias + relu + per-graph max-pool with run compression (no store)
        int gprev = -1;
        float m[8];
#pragma unroll
        for (int j = 0; j < 8; j++) m[j] = 0.f;
#pragma unroll
        for (int i = 0; i < 8; i++) {
            int row = r0 + nlo + i;
            int gj = (row < nrows) ? g_nodeg[row] : -1;
            float v[8];
            if (gj >= 0) {
#pragma unroll
                for (int j = 0; j < 8; j++) v[j] = fmaxf(acc[i][j] + bv[j], 0.f);
            }
            if (gj != gprev) {
                if (gprev >= 0) {
#pragma unroll
                    for (int j = 0; j < 8; j++)
                        atomicMax(&g_pool[gprev * 128 + clo + j], __float_as_int(m[j]));
                }
                if (gj >= 0) {
#pragma unroll
                    for (int j = 0; j < 8; j++) m[j] = v[j];
                }
            } else if (gj >= 0) {
#pragma unroll
                for (int j = 0; j < 8; j++) m[j] = fmaxf(m[j], v[j]);
            }
            gprev = gj;
        }
        if (gprev >= 0) {
#pragma unroll
            for (int j = 0; j < 8; j++)
                atomicMax(&g_pool[gprev * 128 + clo + j], __float_as_int(m[j]));
        }
    } else {
#pragma unroll
        for (int i = 0; i < 8; i++) {
            int row = r0 + nlo + i;
            if (row >= nrows) continue;
            float o[8];
#pragma unroll
            for (int j = 0; j < 8; j++) {
                float v = acc[i][j];
                if (EPI >= 1) v += bv[j];
                if (EPI == 1) v = fmaxf(v, 0.f);
                o[j] = v;
            }
            *(float4*)&Y[(size_t)row * COUT + clo]     = *(float4*)&o[0];
            *(float4*)&Y[(size_t)row * COUT + clo + 4] = *(float4*)&o[4];
        }
    }
}

// ---------------- CSR gather (vectorized): O = P @ H ---------------------
// O_i = dis_i * sum_e H[src_e]*w_e + H_i*dis_i^2  (+bias, relu if EPI)
template<int C, bool EPI>
__global__ __launch_bounds__(256)
void gather_kernel(const float* __restrict__ H, float* __restrict__ O,
                   const float* __restrict__ bias) {
    constexpr int L = C / 4;               // threads per node
    int idx = blockIdx.x * 256 + threadIdx.x;
    int node = idx / L;
    int c4 = (idx % L) * 4;
    if (node >= NN) return;
    int s = g_rowptr[node], e = g_rowptr[node + 1];
    float ax = 0.f, ay = 0.f, az = 0.f, aw = 0.f;
    for (int k = s; k < e; k++) {
        float2 ew = g_csr2[k];
        int src = __float_as_int(ew.x);
        float w = ew.y;
        float4 h = *(const float4*)&H[(size_t)src * C + c4];
        ax += h.x * w; ay += h.y * w; az += h.z * w; aw += h.w * w;
    }
    float d = g_dis[node];
    float d2 = d * d;
    float4 hn = *(const float4*)&H[(size_t)node * C + c4];
    float4 o;
    o.x = d * ax + hn.x * d2;
    o.y = d * ay + hn.y * d2;
    o.z = d * az + hn.z * d2;
    o.w = d * aw + hn.w * d2;
    if (EPI) {
        float4 b = *(const float4*)&bias[c4];
        o.x = fmaxf(o.x + b.x, 0.f);
        o.y = fmaxf(o.y + b.y, 0.f);
        o.z = fmaxf(o.z + b.z, 0.f);
        o.w = fmaxf(o.w + b.w, 0.f);
    }
    *(float4*)&O[(size_t)node * C + c4] = o;
}

// ---------------- launch ----------------
extern "C" void kernel_launch(void* const* d_in, const int* in_sizes, int n_in,
                              void* d_out, int out_size) {
    const float* x     = (const float*)d_in[0];
    const void*  ei    = d_in[1];
    const void*  batch = d_in[2];
    const float* nw    = (const float*)d_in[3];
    const float* nbi   = (const float*)d_in[4];
    const float* W1    = (const float*)d_in[5];
    const float* b1    = (const float*)d_in[6];
    const float* W2    = (const float*)d_in[7];
    const float* b2    = (const float*)d_in[8];
    const float* W3    = (const float*)d_in[9];
    const float* b3    = (const float*)d_in[10];
    const float* l1W   = (const float*)d_in[11];
    const float* l1b   = (const float*)d_in[12];
    const float* l2W   = (const float*)d_in[13];
    const float* l2b   = (const float*)d_in[14];
    float* out = (float*)d_out;

    void *pA, *pB, *pC, *pPool;
    cudaGetSymbolAddress(&pA, g_bufA);
    cudaGetSymbolAddress(&pB, g_bufB);
    cudaGetSymbolAddress(&pC, g_bufC);
    cudaGetSymbolAddress(&pPool, g_pool);
    float* fA = (float*)pA;
    float* fB = (float*)pB;
    float* fC = (float*)pC;
    const float* poolf = (const float*)pPool;

    const int NB_SCAN = (NN + SCAN_B - 1) / SCAN_B;

    detect_kernel<<<1, 1>>>(ei, batch);
    init_kernel<<<(GG * 128 + 255) / 256, 256>>>();
    batchinfo_kernel<<<(NN + 255) / 256, 256>>>(batch);
    count_kernel<<<(EE + 255) / 256, 256>>>(ei);
    dis_kernel<<<(NN + 255) / 256, 256>>>();

    scan1_kernel<<<NB_SCAN, SCAN_B>>>();
    scan2_kernel<<<1, SCAN_B>>>(NB_SCAN);
    scan3_kernel<<<(NN + 255) / 256, 256>>>();
    fill_kernel<<<(EE + 255) / 256, 256>>>(ei);

    stats_kernel<<<GG, 128>>>(x, nw, nbi);

    // layer 1: (norm ∘ x) @ W1 -> B(32ch); propagate w/ bias+relu -> A
    tgemm_kernel<128, 32, 16, true, 0><<<(NN + 511) / 512, 256>>>(x, W1, nullptr, fB, NN);
    gather_kernel<32, true><<<(NN * 8 + 255) / 256, 256>>>(fB, fA, b1);

    // layer 2: propagate (32ch) -> C; GEMM 32->64 w/ bias+relu -> B
    gather_kernel<32, false><<<(NN * 8 + 255) / 256, 256>>>(fA, fC, nullptr);
    tgemm_kernel<32, 64, 16, false, 1><<<(NN + 255) / 256, 256>>>(fC, W2, b2, fB, NN);

    // layer 3: propagate (64ch) -> A; GEMM 64->128 w/ bias+relu + fused pool
    gather_kernel<64, false><<<(NN * 16 + 255) / 256, 256>>>(fB, fA, nullptr);
    tgemm_kernel<64, 128, 16, false, 2><<<(NN + 127) / 128, 256>>>(fA, W3, b3, nullptr, NN);

    // head: pooled[G,128] @ l1W (+relu) -> B[G,256]; @ l2W (+bias) -> out[G,128]
    tgemm_kernel<128, 256, 16, false, 1><<<(GG + 63) / 64, 256>>>(poolf, l1W, l1b, fB, GG);
    tgemm_kernel<256, 128, 16, false, 3><<<(GG + 127) / 128, 256>>>(fB, l2W, l2b, out, GG);
}

// round 4
// speedup vs baseline: 2.3283x; 1.0506x over previous
#include <cuda_runtime.h>
#include <cstdint>
#include <cstddef>

#define NN   200000
#define EE   800000
#define FIN  128
#define GG   8000
#define SCAN_B 512

// ---------------- device scratch ----------------
__device__ float g_bufA[(size_t)NN * 128];
__device__ float g_bufB[(size_t)NN * 128];
__device__ float g_bufC[(size_t)NN * 128];
__device__ float g_dis[NN];
__device__ int   g_cnt[NN];
__device__ int   g_rowptr[NN + 1];
__device__ int   g_fill[NN];
__device__ float2 g_csr2[EE];          // packed {src_bits, dis[src]}
__device__ int   g_bsum[SCAN_B];
__device__ int   g_boff[SCAN_B];
__device__ int   g_gptr[GG + 1];
__device__ int   g_nodeg[NN];
__device__ float g_na[GG * 128];
__device__ float g_nb[GG * 128];
__device__ int   g_pool[GG * 128];     // float bits; post-relu >= 0 so int max == float max
__device__ int   g_ei64;
__device__ int   g_b64;

__device__ __forceinline__ long long ld_idx(const void* p, long long i, int is64) {
    if (is64) return ((const long long*)p)[i];
    return (long long)((const int*)p)[i];
}

// ---------------- packed f32x2 helpers ----------------
__device__ __forceinline__ unsigned long long pk2(float lo, float hi) {
    unsigned long long r;
    asm("mov.b64 %0, {%1, %2};" : "=l"(r) : "f"(lo), "f"(hi));
    return r;
}
__device__ __forceinline__ void upk2(float& lo, float& hi, unsigned long long v) {
    asm("mov.b64 {%0, %1}, %2;" : "=f"(lo), "=f"(hi) : "l"(v));
}
__device__ __forceinline__ void fma2(unsigned long long& d,
                                     unsigned long long a, unsigned long long b) {
    asm("fma.rn.f32x2 %0, %1, %2, %0;" : "+l"(d) : "l"(a), "l"(b));
}

// ---------------- dtype width detection ----------------
__global__ void detect_kernel(const void* ei, const void* batch) {
    if (threadIdx.x == 0 && blockIdx.x == 0) {
        const long long* p = (const long long*)ei;
        int ok = 1;
        for (int i = 0; i < 32; i++) { long long v = p[i]; if (v < 0 || v >= NN) ok = 0; }
        g_ei64 = ok;
        const long long* q = (const long long*)batch;
        int ok2 = 1;
        for (int i = 0; i < 32; i++) { long long v = q[i]; if (v < 0 || v >= GG) ok2 = 0; }
        g_b64 = ok2;
    }
}

// ---------------- merged init ----------------
__global__ void init_kernel() {
    int i = blockIdx.x * blockDim.x + threadIdx.x;
    if (i < NN) g_cnt[i] = 0;
    if (i < GG * 128) g_pool[i] = 0;
}

// nodeg + graph boundary pointers (batch sorted)
__global__ void batchinfo_kernel(const void* __restrict__ batch) {
    int i = blockIdx.x * blockDim.x + threadIdx.x;
    if (i >= NN) return;
    int is64 = g_b64;
    int bi = (int)ld_idx(batch, i, is64);
    g_nodeg[i] = bi;
    if (i == 0) {
        for (int g = 0; g <= bi; g++) g_gptr[g] = 0;
    } else {
        int bp = (int)ld_idx(batch, i - 1, is64);
        for (int g = bp + 1; g <= bi; g++) g_gptr[g] = i;
    }
    if (i == NN - 1) {
        for (int g = bi + 1; g <= GG; g++) g_gptr[g] = NN;
    }
}

// ---------------- degree + inv-sqrt ----------------
__global__ void count_kernel(const void* __restrict__ ei) {
    int i = blockIdx.x * blockDim.x + threadIdx.x;
    if (i >= EE) return;
    int dst = (int)ld_idx(ei, (long long)EE + i, g_ei64);
    atomicAdd(&g_cnt[dst], 1);
}
__global__ void dis_kernel() {
    int i = blockIdx.x * blockDim.x + threadIdx.x;
    if (i < NN) g_dis[i] = rsqrtf(1.0f + (float)g_cnt[i]);
}

// ---------------- exclusive scan of g_cnt -> g_rowptr ----------------
__global__ void scan1_kernel() {
    __shared__ int s[SCAN_B];
    int tid = threadIdx.x;
    int i = blockIdx.x * SCAN_B + tid;
    int v = (i < NN) ? g_cnt[i] : 0;
    s[tid] = v;
    __syncthreads();
    for (int off = 1; off < SCAN_B; off <<= 1) {
        int t = (tid >= off) ? s[tid - off] : 0;
        __syncthreads();
        s[tid] += t;
        __syncthreads();
    }
    if (i < NN) g_rowptr[i] = s[tid] - v;
    if (tid == SCAN_B - 1) g_bsum[blockIdx.x] = s[tid];
}
__global__ void scan2_kernel(int nb) {
    __shared__ int s[SCAN_B];
    int tid = threadIdx.x;
    int v = (tid < nb) ? g_bsum[tid] : 0;
    s[tid] = v;
    __syncthreads();
    for (int off = 1; off < SCAN_B; off <<= 1) {
        int t = (tid >= off) ? s[tid - off] : 0;
        __syncthreads();
        s[tid] += t;
        __syncthreads();
    }
    g_boff[tid] = s[tid] - v;
}
__global__ void scan3_kernel() {
    int i = blockIdx.x * blockDim.x + threadIdx.x;
    if (i < NN) {
        int v = g_rowptr[i] + g_boff[i / SCAN_B];
        g_rowptr[i] = v;
        g_fill[i] = v;
    }
    if (i == 0) g_rowptr[NN] = EE;
}

// ---------------- CSR fill (packed) ----------------
__global__ void fill_kernel(const void* __restrict__ ei) {
    int i = blockIdx.x * blockDim.x + threadIdx.x;
    if (i >= EE) return;
    int is64 = g_ei64;
    int src = (int)ld_idx(ei, i, is64);
    int dst = (int)ld_idx(ei, (long long)EE + i, is64);
    int pos = atomicAdd(&g_fill[dst], 1);
    g_csr2[pos] = make_float2(__int_as_float(src), g_dis[src]);
}

// ---------------- instance norm stats -> affine (v*na + nb) --------------
__global__ void stats_kernel(const float* __restrict__ x,
                             const float* __restrict__ wp,
                             const float* __restrict__ bp) {
    int g = blockIdx.x;
    int c = threadIdx.x;   // 128
    int s = g_gptr[g], e = g_gptr[g + 1];
    if (s >= e) { g_na[g * 128 + c] = 0.f; g_nb[g * 128 + c] = 0.f; return; }
    float w = wp[0], b = bp[0];
    float sum = 0.f, sq = 0.f;
    for (int i = s; i < e; i++) {
        float v = x[(size_t)i * FIN + c];
        sum += v; sq += v * v;
    }
    float cnt  = (float)(e - s);
    float mean = sum / cnt;
    float var  = sq / cnt - mean * mean;
    float inv  = rsqrtf(var + 1e-5f);
    float na = inv * w;
    g_na[g * 128 + c] = na;
    g_nb[g * 128 + c] = b - mean * na;
}

// ---------------- register-tiled GEMM with packed f32x2 FMA --------------
// Y[R,COUT] = X[R,CIN] @ W.  8x8 thread tile as 4 row-pairs x 8 cols of
// 64-bit packed accumulators.  NORM: fuse instance-norm affine into X load.
// EPI: 0 plain, 1 bias+relu, 2 bias+relu+max-pool (NO store), 3 bias only.
template<int CIN, int COUT, int KC, bool NORM, int EPI>
__global__ __launch_bounds__(256, 2)
void tgemm_kernel(const float* __restrict__ X, const float* __restrict__ W,
                  const float* __restrict__ bias, float* __restrict__ Y,
                  int nrows) {
    constexpr int NT = 8;
    constexpr int TC = COUT / NT;         // threads along cols
    constexpr int RG = 256 / TC;          // row groups per block
    constexpr int MB = RG * 8;            // rows per block
    constexpr int KQ = KC / 4;

    __shared__ __align__(16) float sXT[KC * MB];   // transposed: [k][row]
    __shared__ __align__(16) float sW[KC * COUT];  // [k][col]

    int tid = threadIdx.x;
    int r0 = blockIdx.x * MB;
    int grp = tid / TC;
    int clo = (tid % TC) * NT;
    int nlo = grp * 8;

    unsigned long long accp[4][8];
#pragma unroll
    for (int p = 0; p < 4; p++)
#pragma unroll
        for (int j = 0; j < 8; j++) accp[p][j] = 0ull;

    for (int k0 = 0; k0 < CIN; k0 += KC) {
        const float4* Wsrc = (const float4*)(W + (size_t)k0 * COUT);
#pragma unroll
        for (int i = tid; i < KC * COUT / 4; i += 256)
            ((float4*)sW)[i] = Wsrc[i];
        for (int i = tid; i < MB * KQ; i += 256) {
            int rl = i / KQ;
            int kq = i % KQ;
            int row = r0 + rl;
            float4 v = make_float4(0.f, 0.f, 0.f, 0.f);
            if (row < nrows) {
                v = *(const float4*)&X[(size_t)row * CIN + k0 + kq * 4];
                if (NORM) {
                    int g = g_nodeg[row];
                    const float4 na = *(const float4*)&g_na[g * 128 + k0 + kq * 4];
                    const float4 nb = *(const float4*)&g_nb[g * 128 + k0 + kq * 4];
                    v.x = v.x * na.x + nb.x; v.y = v.y * na.y + nb.y;
                    v.z = v.z * na.z + nb.z; v.w = v.w * na.w + nb.w;
                }
            }
            int kk = kq * 4;
            sXT[(kk + 0) * MB + rl] = v.x;
            sXT[(kk + 1) * MB + rl] = v.y;
            sXT[(kk + 2) * MB + rl] = v.z;
            sXT[(kk + 3) * MB + rl] = v.w;
        }
        __syncthreads();

#pragma unroll
        for (int k = 0; k < KC; k++) {
            // row pairs: free from transposed layout (128-bit LDS)
            ulonglong2 xa = *(const ulonglong2*)&sXT[k * MB + nlo];
            ulonglong2 xb = *(const ulonglong2*)&sXT[k * MB + nlo + 4];
            unsigned long long xp[4] = { xa.x, xa.y, xb.x, xb.y };
            float4 wa = *(const float4*)&sW[k * COUT + clo];
            float4 wb = *(const float4*)&sW[k * COUT + clo + 4];
            unsigned long long wp_[8] = {
                pk2(wa.x, wa.x), pk2(wa.y, wa.y), pk2(wa.z, wa.z), pk2(wa.w, wa.w),
                pk2(wb.x, wb.x), pk2(wb.y, wb.y), pk2(wb.z, wb.z), pk2(wb.w, wb.w) };
#pragma unroll
            for (int p = 0; p < 4; p++)
#pragma unroll
                for (int j = 0; j < 8; j++)
                    fma2(accp[p][j], xp[p], wp_[j]);
        }
        __syncthreads();
    }

    // unpack accumulators
    float acc[8][8];
#pragma unroll
    for (int p = 0; p < 4; p++)
#pragma unroll
        for (int j = 0; j < 8; j++)
            upk2(acc[2 * p][j], acc[2 * p + 1][j], accp[p][j]);

    float bv[8];
    if (EPI >= 1) {
        *(float4*)&bv[0] = *(const float4*)&bias[clo];
        *(float4*)&bv[4] = *(const float4*)&bias[clo + 4];
    }

    if (EPI == 2) {
        int gprev = -1;
        float m[8];
#pragma unroll
        for (int j = 0; j < 8; j++) m[j] = 0.f;
#pragma unroll
        for (int i = 0; i < 8; i++) {
            int row = r0 + nlo + i;
            int gj = (row < nrows) ? g_nodeg[row] : -1;
            float v[8];
            if (gj >= 0) {
#pragma unroll
                for (int j = 0; j < 8; j++) v[j] = fmaxf(acc[i][j] + bv[j], 0.f);
            }
            if (gj != gprev) {
                if (gprev >= 0) {
#pragma unroll
                    for (int j = 0; j < 8; j++)
                        atomicMax(&g_pool[gprev * 128 + clo + j], __float_as_int(m[j]));
                }
                if (gj >= 0) {
#pragma unroll
                    for (int j = 0; j < 8; j++) m[j] = v[j];
                }
            } else if (gj >= 0) {
#pragma unroll
                for (int j = 0; j < 8; j++) m[j] = fmaxf(m[j], v[j]);
            }
            gprev = gj;
        }
        if (gprev >= 0) {
#pragma unroll
            for (int j = 0; j < 8; j++)
                atomicMax(&g_pool[gprev * 128 + clo + j], __float_as_int(m[j]));
        }
    } else {
#pragma unroll
        for (int i = 0; i < 8; i++) {
            int row = r0 + nlo + i;
            if (row >= nrows) continue;
            float o[8];
#pragma unroll
            for (int j = 0; j < 8; j++) {
                float v = acc[i][j];
                if (EPI >= 1) v += bv[j];
                if (EPI == 1) v = fmaxf(v, 0.f);
                o[j] = v;
            }
            *(float4*)&Y[(size_t)row * COUT + clo]     = *(float4*)&o[0];
            *(float4*)&Y[(size_t)row * COUT + clo + 4] = *(float4*)&o[4];
        }
    }
}

// ---------------- CSR gather (vectorized): O = P @ H ---------------------
template<int C, bool EPI>
__global__ __launch_bounds__(256)
void gather_kernel(const float* __restrict__ H, float* __restrict__ O,
                   const float* __restrict__ bias) {
    constexpr int L = C / 4;
    int idx = blockIdx.x * 256 + threadIdx.x;
    int node = idx / L;
    int c4 = (idx % L) * 4;
    if (node >= NN) return;
    int s = g_rowptr[node], e = g_rowptr[node + 1];
    float ax = 0.f, ay = 0.f, az = 0.f, aw = 0.f;
    for (int k = s; k < e; k++) {
        float2 ew = g_csr2[k];
        int src = __float_as_int(ew.x);
        float w = ew.y;
        float4 h = *(const float4*)&H[(size_t)src * C + c4];
        ax += h.x * w; ay += h.y * w; az += h.z * w; aw += h.w * w;
    }
    float d = g_dis[node];
    float d2 = d * d;
    float4 hn = *(const float4*)&H[(size_t)node * C + c4];
    float4 o;
    o.x = d * ax + hn.x * d2;
    o.y = d * ay + hn.y * d2;
    o.z = d * az + hn.z * d2;
    o.w = d * aw + hn.w * d2;
    if (EPI) {
        float4 b = *(const float4*)&bias[c4];
        o.x = fmaxf(o.x + b.x, 0.f);
        o.y = fmaxf(o.y + b.y, 0.f);
        o.z = fmaxf(o.z + b.z, 0.f);
        o.w = fmaxf(o.w + b.w, 0.f);
    }
    *(float4*)&O[(size_t)node * C + c4] = o;
}

// ---------------- launch ----------------
extern "C" void kernel_launch(void* const* d_in, const int* in_sizes, int n_in,
                              void* d_out, int out_size) {
    const float* x     = (const float*)d_in[0];
    const void*  ei    = d_in[1];
    const void*  batch = d_in[2];
    const float* nw    = (const float*)d_in[3];
    const float* nbi   = (const float*)d_in[4];
    const float* W1    = (const float*)d_in[5];
    const float* b1    = (const float*)d_in[6];
    const float* W2    = (const float*)d_in[7];
    const float* b2    = (const float*)d_in[8];
    const float* W3    = (const float*)d_in[9];
    const float* b3    = (const float*)d_in[10];
    const float* l1W   = (const float*)d_in[11];
    const float* l1b   = (const float*)d_in[12];
    const float* l2W   = (const float*)d_in[13];
    const float* l2b   = (const float*)d_in[14];
    float* out = (float*)d_out;

    void *pA, *pB, *pC, *pPool;
    cudaGetSymbolAddress(&pA, g_bufA);
    cudaGetSymbolAddress(&pB, g_bufB);
    cudaGetSymbolAddress(&pC, g_bufC);
    cudaGetSymbolAddress(&pPool, g_pool);
    float* fA = (float*)pA;
    float* fB = (float*)pB;
    float* fC = (float*)pC;
    const float* poolf = (const float*)pPool;

    const int NB_SCAN = (NN + SCAN_B - 1) / SCAN_B;

    detect_kernel<<<1, 1>>>(ei, batch);
    init_kernel<<<(GG * 128 + 255) / 256, 256>>>();
    batchinfo_kernel<<<(NN + 255) / 256, 256>>>(batch);
    count_kernel<<<(EE + 255) / 256, 256>>>(ei);
    dis_kernel<<<(NN + 255) / 256, 256>>>();

    scan1_kernel<<<NB_SCAN, SCAN_B>>>();
    scan2_kernel<<<1, SCAN_B>>>(NB_SCAN);
    scan3_kernel<<<(NN + 255) / 256, 256>>>();
    fill_kernel<<<(EE + 255) / 256, 256>>>(ei);

    stats_kernel<<<GG, 128>>>(x, nw, nbi);

    // layer 1: (norm ∘ x) @ W1 -> B(32ch); propagate w/ bias+relu -> A
    tgemm_kernel<128, 32, 16, true, 0><<<(NN + 511) / 512, 256>>>(x, W1, nullptr, fB, NN);
    gather_kernel<32, true><<<(NN * 8 + 255) / 256, 256>>>(fB, fA, b1);

    // layer 2: propagate (32ch) -> C; GEMM 32->64 w/ bias+relu -> B
    gather_kernel<32, false><<<(NN * 8 + 255) / 256, 256>>>(fA, fC, nullptr);
    tgemm_kernel<32, 64, 16, false, 1><<<(NN + 255) / 256, 256>>>(fC, W2, b2, fB, NN);

    // layer 3: propagate (64ch) -> A; GEMM 64->128 w/ bias+relu + fused pool
    gather_kernel<64, false><<<(NN * 16 + 255) / 256, 256>>>(fB, fA, nullptr);
    tgemm_kernel<64, 128, 16, false, 2><<<(NN + 127) / 128, 256>>>(fA, W3, b3, nullptr, NN);

    // head: pooled[G,128] @ l1W (+relu) -> B[G,256]; @ l2W (+bias) -> out[G,128]
    tgemm_kernel<128, 256, 16, false, 1><<<(GG + 63) / 64, 256>>>(poolf, l1W, l1b, fB, GG);
    tgemm_kernel<256, 128, 16, false, 3><<<(GG + 127) / 128, 256>>>(fB, l2W, l2b, out, GG);
}

// round 5
// speedup vs baseline: 2.4013x; 1.0314x over previous
#include <cuda_runtime.h>
#include <cstdint>
#include <cstddef>

#define NN   200000
#define EE   800000
#define FIN  128
#define GG   8000
#define SCAN_B 512

// ---------------- device scratch ----------------
__device__ float g_bufA[(size_t)NN * 128];
__device__ float g_bufB[(size_t)NN * 128];
__device__ float g_bufC[(size_t)NN * 128];
__device__ float g_dis[NN];
__device__ int   g_cnt[NN];
__device__ int   g_rowptr[NN + 1];
__device__ int   g_fill[NN];
__device__ float2 g_csr2[EE];          // packed {src_bits, dis[src]}
__device__ int   g_bsum[SCAN_B];
__device__ int   g_boff[SCAN_B];
__device__ int   g_gptr[GG + 1];
__device__ int   g_nodeg[NN];
__device__ float g_na[GG * 128];
__device__ float g_nb[GG * 128];
__device__ int   g_pool[GG * 128];     // float bits; post-relu >= 0 so int max == float max
__device__ int   g_ei64;
__device__ int   g_b64;

__device__ __forceinline__ long long ld_idx(const void* p, long long i, int is64) {
    if (is64) return ((const long long*)p)[i];
    return (long long)((const int*)p)[i];
}

// ---------------- packed f32x2 helpers ----------------
__device__ __forceinline__ unsigned long long pk2(float lo, float hi) {
    unsigned long long r;
    asm("mov.b64 %0, {%1, %2};" : "=l"(r) : "f"(lo), "f"(hi));
    return r;
}
__device__ __forceinline__ void upk2(float& lo, float& hi, unsigned long long v) {
    asm("mov.b64 {%0, %1}, %2;" : "=f"(lo), "=f"(hi) : "l"(v));
}
__device__ __forceinline__ void fma2(unsigned long long& d,
                                     unsigned long long a, unsigned long long b) {
    asm("fma.rn.f32x2 %0, %1, %2, %0;" : "+l"(d) : "l"(a), "l"(b));
}

// ---------------- dtype width detection (warp-parallel) ----------------
__global__ void detect_kernel(const void* ei, const void* batch) {
    int lane = threadIdx.x;                       // 32 threads
    long long v = ((const long long*)ei)[lane];
    unsigned bad1 = __ballot_sync(0xffffffffu, v < 0 || v >= NN);
    long long q = ((const long long*)batch)[lane];
    unsigned bad2 = __ballot_sync(0xffffffffu, q < 0 || q >= GG);
    if (lane == 0) {
        g_ei64 = (bad1 == 0u);
        g_b64  = (bad2 == 0u);
    }
}

// ---------------- merged init ----------------
__global__ void init_kernel() {
    int i = blockIdx.x * blockDim.x + threadIdx.x;
    if (i < NN) g_cnt[i] = 0;
    if (i < GG * 128) g_pool[i] = 0;
}

// nodeg + graph boundary pointers (batch sorted)
__global__ void batchinfo_kernel(const void* __restrict__ batch) {
    int i = blockIdx.x * blockDim.x + threadIdx.x;
    if (i >= NN) return;
    int is64 = g_b64;
    int bi = (int)ld_idx(batch, i, is64);
    g_nodeg[i] = bi;
    if (i == 0) {
        for (int g = 0; g <= bi; g++) g_gptr[g] = 0;
    } else {
        int bp = (int)ld_idx(batch, i - 1, is64);
        for (int g = bp + 1; g <= bi; g++) g_gptr[g] = i;
    }
    if (i == NN - 1) {
        for (int g = bi + 1; g <= GG; g++) g_gptr[g] = NN;
    }
}

// ---------------- degree ----------------
__global__ void count_kernel(const void* __restrict__ ei) {
    int i = blockIdx.x * blockDim.x + threadIdx.x;
    if (i >= EE) return;
    int dst = (int)ld_idx(ei, (long long)EE + i, g_ei64);
    atomicAdd(&g_cnt[dst], 1);
}

// ---------------- exclusive scan of g_cnt -> g_rowptr (+ dis fused) ------
__global__ void scan1_kernel() {
    __shared__ int s[SCAN_B];
    int tid = threadIdx.x;
    int i = blockIdx.x * SCAN_B + tid;
    int v = (i < NN) ? g_cnt[i] : 0;
    if (i < NN) g_dis[i] = rsqrtf(1.0f + (float)v);
    s[tid] = v;
    __syncthreads();
    for (int off = 1; off < SCAN_B; off <<= 1) {
        int t = (tid >= off) ? s[tid - off] : 0;
        __syncthreads();
        s[tid] += t;
        __syncthreads();
    }
    if (i < NN) g_rowptr[i] = s[tid] - v;
    if (tid == SCAN_B - 1) g_bsum[blockIdx.x] = s[tid];
}
__global__ void scan2_kernel(int nb) {
    __shared__ int s[SCAN_B];
    int tid = threadIdx.x;
    int v = (tid < nb) ? g_bsum[tid] : 0;
    s[tid] = v;
    __syncthreads();
    for (int off = 1; off < SCAN_B; off <<= 1) {
        int t = (tid >= off) ? s[tid - off] : 0;
        __syncthreads();
        s[tid] += t;
        __syncthreads();
    }
    g_boff[tid] = s[tid] - v;
}
__global__ void scan3_kernel() {
    int i = blockIdx.x * blockDim.x + threadIdx.x;
    if (i < NN) {
        int v = g_rowptr[i] + g_boff[i / SCAN_B];
        g_rowptr[i] = v;
        g_fill[i] = v;
    }
    if (i == 0) g_rowptr[NN] = EE;
}

// ---------------- CSR fill (packed) ----------------
__global__ void fill_kernel(const void* __restrict__ ei) {
    int i = blockIdx.x * blockDim.x + threadIdx.x;
    if (i >= EE) return;
    int is64 = g_ei64;
    int src = (int)ld_idx(ei, i, is64);
    int dst = (int)ld_idx(ei, (long long)EE + i, is64);
    int pos = atomicAdd(&g_fill[dst], 1);
    g_csr2[pos] = make_float2(__int_as_float(src), g_dis[src]);
}

// ---------------- instance norm stats -> affine (v*na + nb) --------------
__global__ void stats_kernel(const float* __restrict__ x,
                             const float* __restrict__ wp,
                             const float* __restrict__ bp) {
    int g = blockIdx.x;
    int c = threadIdx.x;   // 128
    int s = g_gptr[g], e = g_gptr[g + 1];
    if (s >= e) { g_na[g * 128 + c] = 0.f; g_nb[g * 128 + c] = 0.f; return; }
    float w = wp[0], b = bp[0];
    float sum = 0.f, sq = 0.f;
    for (int i = s; i < e; i++) {
        float v = x[(size_t)i * FIN + c];
        sum += v; sq += v * v;
    }
    float cnt  = (float)(e - s);
    float mean = sum / cnt;
    float var  = sq / cnt - mean * mean;
    float inv  = rsqrtf(var + 1e-5f);
    float na = inv * w;
    g_na[g * 128 + c] = na;
    g_nb[g * 128 + c] = b - mean * na;
}

// ---------------- register-tiled GEMM with packed f32x2 FMA --------------
// Y[r, col0+c] = sum_k X[r,k] * W[k, col0+c], col0 = blockIdx.y*COUT.
// 8x8 tile as 4 row-pairs x 8 cols of packed u64 accumulators.
// NORM: fuse instance-norm affine into X tile load (CIN must be 128).
// EPI: 0 plain, 1 bias+relu, 2 bias+relu+max-pool (NO store), 3 bias only.
template<int CIN, int COUT, int KC, bool NORM, int EPI>
__global__ __launch_bounds__(256, 2)
void tgemm_kernel(const float* __restrict__ X, const float* __restrict__ W,
                  int ldw, const float* __restrict__ bias,
                  float* __restrict__ Y, int ldy, int nrows) {
    constexpr int NT = 8;
    constexpr int TC = COUT / NT;         // threads along cols
    constexpr int RG = 256 / TC;          // row groups per block
    constexpr int MB = RG * 8;            // rows per block
    constexpr int MBP = MB + 4;           // padded stride (16B-aligned, 2-way max)
    constexpr int KQ = KC / 4;

    __shared__ __align__(16) float sXT[KC * MBP];  // transposed: [k][row]
    __shared__ __align__(16) float sW[KC * COUT];  // [k][col]

    int tid = threadIdx.x;
    int r0 = blockIdx.x * MB;
    int col0 = blockIdx.y * COUT;
    int grp = tid / TC;
    int clo = (tid % TC) * NT;
    int nlo = grp * 8;

    unsigned long long accp[4][8];
#pragma unroll
    for (int p = 0; p < 4; p++)
#pragma unroll
        for (int j = 0; j < 8; j++) accp[p][j] = 0ull;

    for (int k0 = 0; k0 < CIN; k0 += KC) {
#pragma unroll
        for (int i = tid; i < KC * COUT / 4; i += 256) {
            int k = i / (COUT / 4);
            int c4 = (i % (COUT / 4)) * 4;
            *(float4*)&sW[k * COUT + c4] =
                *(const float4*)&W[(size_t)(k0 + k) * ldw + col0 + c4];
        }
        for (int i = tid; i < MB * KQ; i += 256) {
            int rl = i / KQ;
            int kq = i % KQ;
            int row = r0 + rl;
            float4 v = make_float4(0.f, 0.f, 0.f, 0.f);
            if (row < nrows) {
                v = *(const float4*)&X[(size_t)row * CIN + k0 + kq * 4];
                if (NORM) {
                    int g = g_nodeg[row];
                    const float4 na = *(const float4*)&g_na[g * 128 + k0 + kq * 4];
                    const float4 nb = *(const float4*)&g_nb[g * 128 + k0 + kq * 4];
                    v.x = v.x * na.x + nb.x; v.y = v.y * na.y + nb.y;
                    v.z = v.z * na.z + nb.z; v.w = v.w * na.w + nb.w;
                }
            }
            int kk = kq * 4;
            sXT[(kk + 0) * MBP + rl] = v.x;
            sXT[(kk + 1) * MBP + rl] = v.y;
            sXT[(kk + 2) * MBP + rl] = v.z;
            sXT[(kk + 3) * MBP + rl] = v.w;
        }
        __syncthreads();

#pragma unroll
        for (int k = 0; k < KC; k++) {
            ulonglong2 xa = *(const ulonglong2*)&sXT[k * MBP + nlo];
            ulonglong2 xb = *(const ulonglong2*)&sXT[k * MBP + nlo + 4];
            unsigned long long xp[4] = { xa.x, xa.y, xb.x, xb.y };
            float4 wa = *(const float4*)&sW[k * COUT + clo];
            float4 wb = *(const float4*)&sW[k * COUT + clo + 4];
            unsigned long long wp_[8] = {
                pk2(wa.x, wa.x), pk2(wa.y, wa.y), pk2(wa.z, wa.z), pk2(wa.w, wa.w),
                pk2(wb.x, wb.x), pk2(wb.y, wb.y), pk2(wb.z, wb.z), pk2(wb.w, wb.w) };
#pragma unroll
            for (int p = 0; p < 4; p++)
#pragma unroll
                for (int j = 0; j < 8; j++)
                    fma2(accp[p][j], xp[p], wp_[j]);
        }
        __syncthreads();
    }

    float acc[8][8];
#pragma unroll
    for (int p = 0; p < 4; p++)
#pragma unroll
        for (int j = 0; j < 8; j++)
            upk2(acc[2 * p][j], acc[2 * p + 1][j], accp[p][j]);

    float bv[8];
    if (EPI >= 1) {
        *(float4*)&bv[0] = *(const float4*)&bias[col0 + clo];
        *(float4*)&bv[4] = *(const float4*)&bias[col0 + clo + 4];
    }

    if (EPI == 2) {
        int gprev = -1;
        float m[8];
#pragma unroll
        for (int j = 0; j < 8; j++) m[j] = 0.f;
#pragma unroll
        for (int i = 0; i < 8; i++) {
            int row = r0 + nlo + i;
            int gj = (row < nrows) ? g_nodeg[row] : -1;
            float v[8];
            if (gj >= 0) {
#pragma unroll
                for (int j = 0; j < 8; j++) v[j] = fmaxf(acc[i][j] + bv[j], 0.f);
            }
            if (gj != gprev) {
                if (gprev >= 0) {
#pragma unroll
                    for (int j = 0; j < 8; j++)
                        atomicMax(&g_pool[gprev * 128 + col0 + clo + j], __float_as_int(m[j]));
                }
                if (gj >= 0) {
#pragma unroll
                    for (int j = 0; j < 8; j++) m[j] = v[j];
                }
            } else if (gj >= 0) {
#pragma unroll
                for (int j = 0; j < 8; j++) m[j] = fmaxf(m[j], v[j]);
            }
            gprev = gj;
        }
        if (gprev >= 0) {
#pragma unroll
            for (int j = 0; j < 8; j++)
                atomicMax(&g_pool[gprev * 128 + col0 + clo + j], __float_as_int(m[j]));
        }
    } else {
#pragma unroll
        for (int i = 0; i < 8; i++) {
            int row = r0 + nlo + i;
            if (row >= nrows) continue;
            float o[8];
#pragma unroll
            for (int j = 0; j < 8; j++) {
                float v = acc[i][j];
                if (EPI >= 1) v += bv[j];
                if (EPI == 1) v = fmaxf(v, 0.f);
                o[j] = v;
            }
            *(float4*)&Y[(size_t)row * ldy + col0 + clo]     = *(float4*)&o[0];
            *(float4*)&Y[(size_t)row * ldy + col0 + clo + 4] = *(float4*)&o[4];
        }
    }
}

// ---------------- CSR gather (vectorized): O = P @ H ---------------------
template<int C, bool EPI>
__global__ __launch_bounds__(256)
void gather_kernel(const float* __restrict__ H, float* __restrict__ O,
                   const float* __restrict__ bias) {
    constexpr int L = C / 4;
    int idx = blockIdx.x * 256 + threadIdx.x;
    int node = idx / L;
    int c4 = (idx % L) * 4;
    if (node >= NN) return;
    int s = g_rowptr[node], e = g_rowptr[node + 1];
    float ax = 0.f, ay = 0.f, az = 0.f, aw = 0.f;
    for (int k = s; k < e; k++) {
        float2 ew = g_csr2[k];
        int src = __float_as_int(ew.x);
        float w = ew.y;
        float4 h = *(const float4*)&H[(size_t)src * C + c4];
        ax += h.x * w; ay += h.y * w; az += h.z * w; aw += h.w * w;
    }
    float d = g_dis[node];
    float d2 = d * d;
    float4 hn = *(const float4*)&H[(size_t)node * C + c4];
    float4 o;
    o.x = d * ax + hn.x * d2;
    o.y = d * ay + hn.y * d2;
    o.z = d * az + hn.z * d2;
    o.w = d * aw + hn.w * d2;
    if (EPI) {
        float4 b = *(const float4*)&bias[c4];
        o.x = fmaxf(o.x + b.x, 0.f);
        o.y = fmaxf(o.y + b.y, 0.f);
        o.z = fmaxf(o.z + b.z, 0.f);
        o.w = fmaxf(o.w + b.w, 0.f);
    }
    *(float4*)&O[(size_t)node * C + c4] = o;
}

// ---------------- launch ----------------
extern "C" void kernel_launch(void* const* d_in, const int* in_sizes, int n_in,
                              void* d_out, int out_size) {
    const float* x     = (const float*)d_in[0];
    const void*  ei    = d_in[1];
    const void*  batch = d_in[2];
    const float* nw    = (const float*)d_in[3];
    const float* nbi   = (const float*)d_in[4];
    const float* W1    = (const float*)d_in[5];
    const float* b1    = (const float*)d_in[6];
    const float* W2    = (const float*)d_in[7];
    const float* b2    = (const float*)d_in[8];
    const float* W3    = (const float*)d_in[9];
    const float* b3    = (const float*)d_in[10];
    const float* l1W   = (const float*)d_in[11];
    const float* l1b   = (const float*)d_in[12];
    const float* l2W   = (const float*)d_in[13];
    const float* l2b   = (const float*)d_in[14];
    float* out = (float*)d_out;

    void *pA, *pB, *pC, *pPool;
    cudaGetSymbolAddress(&pA, g_bufA);
    cudaGetSymbolAddress(&pB, g_bufB);
    cudaGetSymbolAddress(&pC, g_bufC);
    cudaGetSymbolAddress(&pPool, g_pool);
    float* fA = (float*)pA;
    float* fB = (float*)pB;
    float* fC = (float*)pC;
    const float* poolf = (const float*)pPool;

    const int NB_SCAN = (NN + SCAN_B - 1) / SCAN_B;

    detect_kernel<<<1, 32>>>(ei, batch);
    init_kernel<<<(GG * 128 + 255) / 256, 256>>>();
    batchinfo_kernel<<<(NN + 255) / 256, 256>>>(batch);
    count_kernel<<<(EE + 255) / 256, 256>>>(ei);

    scan1_kernel<<<NB_SCAN, SCAN_B>>>();
    scan2_kernel<<<1, SCAN_B>>>(NB_SCAN);
    scan3_kernel<<<(NN + 255) / 256, 256>>>();
    fill_kernel<<<(EE + 255) / 256, 256>>>(ei);

    stats_kernel<<<GG, 128>>>(x, nw, nbi);

    // layer 1: (norm ∘ x) @ W1 -> B(32ch); propagate w/ bias+relu -> A
    tgemm_kernel<128, 32, 16, true, 0><<<(NN + 511) / 512, 256>>>(x, W1, 32, nullptr, fB, 32, NN);
    gather_kernel<32, true><<<(NN * 8 + 255) / 256, 256>>>(fB, fA, b1);

    // layer 2: propagate (32ch) -> C; GEMM 32->64 w/ bias+relu -> B
    gather_kernel<32, false><<<(NN * 8 + 255) / 256, 256>>>(fA, fC, nullptr);
    tgemm_kernel<32, 64, 32, false, 1><<<(NN + 255) / 256, 256>>>(fC, W2, 64, b2, fB, 64, NN);

    // layer 3: propagate (64ch) -> A; GEMM 64->128 w/ bias+relu + fused pool
    gather_kernel<64, false><<<(NN * 16 + 255) / 256, 256>>>(fB, fA, nullptr);
    tgemm_kernel<64, 128, 32, false, 2><<<(NN + 127) / 128, 256>>>(fA, W3, 128, b3, nullptr, 128, NN);

    // head: pooled[G,128] @ l1W (+relu) -> B[G,256]; @ l2W (+bias) -> out[G,128]
    {
        dim3 grid1((GG + 255) / 256, 4);   // 256 cols in 4 tiles of 64
        tgemm_kernel<128, 64, 32, false, 1><<<grid1, 256>>>(poolf, l1W, 256, l1b, fB, 256, GG);
        dim3 grid2((GG + 255) / 256, 2);   // 128 cols in 2 tiles of 64
        tgemm_kernel<256, 64, 32, false, 3><<<grid2, 256>>>(fB, l2W, 128, l2b, out, 128, GG);
    }
}

// round 6
// speedup vs baseline: 2.5939x; 1.0802x over previous
#include <cuda_runtime.h>
#include <cuda_bf16.h>
#include <cstdint>
#include <cstddef>

#define NN   200000
#define EE   800000
#define FIN  128
#define GG   8000
#define SCAN_B 512

// ---------------- device scratch ----------------
__device__ float g_bufA[(size_t)NN * 128];
__device__ float g_bufB[(size_t)NN * 128];
__device__ float g_bufC[(size_t)NN * 128];
__device__ float g_dis[NN];
__device__ int   g_cnt[NN];
__device__ int   g_rowptr[NN + 1];
__device__ int   g_fill[NN];
__device__ float2 g_csr2[EE];          // packed {src_bits, dis[src]}
__device__ int   g_bsum[SCAN_B];
__device__ int   g_boff[SCAN_B];
__device__ int   g_gptr[GG + 1];
__device__ int   g_nodeg[NN];
__device__ float g_na[GG * 128];
__device__ float g_nb[GG * 128];
__device__ float g_pool[GG * 128];
__device__ int   g_ei64;
__device__ int   g_b64;

__device__ __forceinline__ long long ld_idx(const void* p, long long i, int is64) {
    if (is64) return ((const long long*)p)[i];
    return (long long)((const int*)p)[i];
}

// ---------------- dtype width detection (warp-parallel) ----------------
__global__ void detect_kernel(const void* ei, const void* batch) {
    int lane = threadIdx.x;
    long long v = ((const long long*)ei)[lane];
    unsigned bad1 = __ballot_sync(0xffffffffu, v < 0 || v >= NN);
    long long q = ((const long long*)batch)[lane];
    unsigned bad2 = __ballot_sync(0xffffffffu, q < 0 || q >= GG);
    if (lane == 0) {
        g_ei64 = (bad1 == 0u);
        g_b64  = (bad2 == 0u);
    }
}

// ---------------- init ----------------
__global__ void init_kernel() {
    int i = blockIdx.x * blockDim.x + threadIdx.x;
    if (i < NN) g_cnt[i] = 0;
}

// nodeg + graph boundary pointers (batch sorted)
__global__ void batchinfo_kernel(const void* __restrict__ batch) {
    int i = blockIdx.x * blockDim.x + threadIdx.x;
    if (i >= NN) return;
    int is64 = g_b64;
    int bi = (int)ld_idx(batch, i, is64);
    g_nodeg[i] = bi;
    if (i == 0) {
        for (int g = 0; g <= bi; g++) g_gptr[g] = 0;
    } else {
        int bp = (int)ld_idx(batch, i - 1, is64);
        for (int g = bp + 1; g <= bi; g++) g_gptr[g] = i;
    }
    if (i == NN - 1) {
        for (int g = bi + 1; g <= GG; g++) g_gptr[g] = NN;
    }
}

// ---------------- degree ----------------
__global__ void count_kernel(const void* __restrict__ ei) {
    int i = blockIdx.x * blockDim.x + threadIdx.x;
    if (i >= EE) return;
    int dst = (int)ld_idx(ei, (long long)EE + i, g_ei64);
    atomicAdd(&g_cnt[dst], 1);
}

// ---------------- exclusive scan of g_cnt -> g_rowptr (+ dis fused) ------
__global__ void scan1_kernel() {
    __shared__ int s[SCAN_B];
    int tid = threadIdx.x;
    int i = blockIdx.x * SCAN_B + tid;
    int v = (i < NN) ? g_cnt[i] : 0;
    if (i < NN) g_dis[i] = rsqrtf(1.0f + (float)v);
    s[tid] = v;
    __syncthreads();
    for (int off = 1; off < SCAN_B; off <<= 1) {
        int t = (tid >= off) ? s[tid - off] : 0;
        __syncthreads();
        s[tid] += t;
        __syncthreads();
    }
    if (i < NN) g_rowptr[i] = s[tid] - v;
    if (tid == SCAN_B - 1) g_bsum[blockIdx.x] = s[tid];
}
__global__ void scan2_kernel(int nb) {
    __shared__ int s[SCAN_B];
    int tid = threadIdx.x;
    int v = (tid < nb) ? g_bsum[tid] : 0;
    s[tid] = v;
    __syncthreads();
    for (int off = 1; off < SCAN_B; off <<= 1) {
        int t = (tid >= off) ? s[tid - off] : 0;
        __syncthreads();
        s[tid] += t;
        __syncthreads();
    }
    g_boff[tid] = s[tid] - v;
}
__global__ void scan3_kernel() {
    int i = blockIdx.x * blockDim.x + threadIdx.x;
    if (i < NN) {
        int v = g_rowptr[i] + g_boff[i / SCAN_B];
        g_rowptr[i] = v;
        g_fill[i] = v;
    }
    if (i == 0) g_rowptr[NN] = EE;
}

// ---------------- CSR fill (packed) ----------------
__global__ void fill_kernel(const void* __restrict__ ei) {
    int i = blockIdx.x * blockDim.x + threadIdx.x;
    if (i >= EE) return;
    int is64 = g_ei64;
    int src = (int)ld_idx(ei, i, is64);
    int dst = (int)ld_idx(ei, (long long)EE + i, is64);
    int pos = atomicAdd(&g_fill[dst], 1);
    g_csr2[pos] = make_float2(__int_as_float(src), g_dis[src]);
}

// ---------------- instance norm stats -> affine (v*na + nb) --------------
__global__ void stats_kernel(const float* __restrict__ x,
                             const float* __restrict__ wp,
                             const float* __restrict__ bp) {
    int g = blockIdx.x;
    int c = threadIdx.x;   // 128
    int s = g_gptr[g], e = g_gptr[g + 1];
    if (s >= e) { g_na[g * 128 + c] = 0.f; g_nb[g * 128 + c] = 0.f; return; }
    float w = wp[0], b = bp[0];
    float sum = 0.f, sq = 0.f;
    for (int i = s; i < e; i++) {
        float v = x[(size_t)i * FIN + c];
        sum += v; sq += v * v;
    }
    float cnt  = (float)(e - s);
    float mean = sum / cnt;
    float var  = sq / cnt - mean * mean;
    float inv  = rsqrtf(var + 1e-5f);
    float na = inv * w;
    g_na[g * 128 + c] = na;
    g_nb[g * 128 + c] = b - mean * na;
}

// ---------------- bf16x3 split tensor-core GEMM --------------------------
// Y[r, col0+c] = sum_k X[r,k] * W[k, col0+c]   (error: only lo*lo dropped)
// Block: 256 threads = 8 warps, 128 rows/block; warp w -> rows [w*16, w*16+16).
// smem: X chunk [128][KCH] split hi/lo bf16 (stride 40: ldmatrix conflict-free),
//       W chunk as Wt [COUT][KCH] split hi/lo (n-major, k contiguous).
// EPI: 0 plain, 1 bias+relu, 3 bias only.  NORM: fuse instnorm affine (CIN=128).
template<int CIN, int COUT, bool NORM, int EPI>
__global__ __launch_bounds__(256)
void mma_gemm(const float* __restrict__ X, const float* __restrict__ W,
              int ldw, const float* __restrict__ bias,
              float* __restrict__ Y, int ldy, int nrows) {
    constexpr int KCH = 32;
    constexpr int ST  = 40;              // padded stride (bf16 elems), 80B rows
    constexpr int NT  = COUT / 8;        // n-tiles

    __shared__ __align__(16) __nv_bfloat16 sXhi[128 * ST];
    __shared__ __align__(16) __nv_bfloat16 sXlo[128 * ST];
    __shared__ __align__(16) __nv_bfloat16 sWhi[COUT * ST];
    __shared__ __align__(16) __nv_bfloat16 sWlo[COUT * ST];

    int tid = threadIdx.x;
    int wid = tid >> 5;
    int lane = tid & 31;
    int r0 = blockIdx.x * 128;
    int col0 = blockIdx.y * COUT;

    float acc[NT][4];
#pragma unroll
    for (int n = 0; n < NT; n++)
#pragma unroll
        for (int j = 0; j < 4; j++) acc[n][j] = 0.f;

    // ldmatrix base addresses (per-lane)
    int arow = lane & 15;                    // A: rows 0..15
    int akoff = (lane >> 4) * 8;             // A: +8 k for lanes 16..31
    unsigned aAhi = (unsigned)__cvta_generic_to_shared(
        &sXhi[(wid * 16 + arow) * ST + akoff]);
    unsigned aAlo = (unsigned)__cvta_generic_to_shared(
        &sXlo[(wid * 16 + arow) * ST + akoff]);
    int brow = lane & 7;                     // B: n-rows 0..7
    int bkoff = ((lane >> 3) & 1) * 8;       // B: +8 k for lanes 8..15
    unsigned aBhi = (unsigned)__cvta_generic_to_shared(&sWhi[brow * ST + bkoff]);
    unsigned aBlo = (unsigned)__cvta_generic_to_shared(&sWlo[brow * ST + bkoff]);

    for (int k0 = 0; k0 < CIN; k0 += KCH) {
        // ---- X chunk: load fp32, split to hi/lo bf16 ----
        for (int i = tid; i < 128 * (KCH / 4); i += 256) {
            int rl = i / (KCH / 4);
            int kq = i % (KCH / 4);
            int row = r0 + rl;
            float4 v = make_float4(0.f, 0.f, 0.f, 0.f);
            if (row < nrows) {
                v = *(const float4*)&X[(size_t)row * CIN + k0 + kq * 4];
                if (NORM) {
                    int g = g_nodeg[row];
                    const float4 na = *(const float4*)&g_na[g * 128 + k0 + kq * 4];
                    const float4 nb = *(const float4*)&g_nb[g * 128 + k0 + kq * 4];
                    v.x = v.x * na.x + nb.x; v.y = v.y * na.y + nb.y;
                    v.z = v.z * na.z + nb.z; v.w = v.w * na.w + nb.w;
                }
            }
            float vv[4] = { v.x, v.y, v.z, v.w };
            int base = rl * ST + kq * 4;
#pragma unroll
            for (int t = 0; t < 4; t++) {
                __nv_bfloat16 h = __float2bfloat16_rn(vv[t]);
                __nv_bfloat16 l = __float2bfloat16_rn(vv[t] - __bfloat162float(h));
                sXhi[base + t] = h;
                sXlo[base + t] = l;
            }
        }
        // ---- W chunk: [k][c] global -> Wt [c][k] smem, split ----
        for (int i = tid; i < KCH * COUT; i += 256) {
            int k = i / COUT;
            int c = i % COUT;
            float w = W[(size_t)(k0 + k) * ldw + col0 + c];
            __nv_bfloat16 h = __float2bfloat16_rn(w);
            __nv_bfloat16 l = __float2bfloat16_rn(w - __bfloat162float(h));
            sWhi[c * ST + k] = h;
            sWlo[c * ST + k] = l;
        }
        __syncthreads();

#pragma unroll
        for (int ks = 0; ks < KCH / 16; ks++) {
            unsigned ah0, ah1, ah2, ah3, al0, al1, al2, al3;
            asm volatile("ldmatrix.sync.aligned.m8n8.x4.shared.b16 {%0,%1,%2,%3}, [%4];"
                         : "=r"(ah0), "=r"(ah1), "=r"(ah2), "=r"(ah3)
                         : "r"(aAhi + ks * 32u));
            asm volatile("ldmatrix.sync.aligned.m8n8.x4.shared.b16 {%0,%1,%2,%3}, [%4];"
                         : "=r"(al0), "=r"(al1), "=r"(al2), "=r"(al3)
                         : "r"(aAlo + ks * 32u));
#pragma unroll
            for (int n = 0; n < NT; n++) {
                unsigned bh0, bh1, bl0, bl1;
                asm volatile("ldmatrix.sync.aligned.m8n8.x2.shared.b16 {%0,%1}, [%2];"
                             : "=r"(bh0), "=r"(bh1)
                             : "r"(aBhi + (unsigned)(n * 8 * ST * 2) + ks * 32u));
                asm volatile("ldmatrix.sync.aligned.m8n8.x2.shared.b16 {%0,%1}, [%2];"
                             : "=r"(bl0), "=r"(bl1)
                             : "r"(aBlo + (unsigned)(n * 8 * ST * 2) + ks * 32u));
                asm volatile("mma.sync.aligned.m16n8k16.row.col.f32.bf16.bf16.f32 "
                             "{%0,%1,%2,%3},{%4,%5,%6,%7},{%8,%9},{%0,%1,%2,%3};"
                             : "+f"(acc[n][0]), "+f"(acc[n][1]), "+f"(acc[n][2]), "+f"(acc[n][3])
                             : "r"(ah0), "r"(ah1), "r"(ah2), "r"(ah3), "r"(bh0), "r"(bh1));
                asm volatile("mma.sync.aligned.m16n8k16.row.col.f32.bf16.bf16.f32 "
                             "{%0,%1,%2,%3},{%4,%5,%6,%7},{%8,%9},{%0,%1,%2,%3};"
                             : "+f"(acc[n][0]), "+f"(acc[n][1]), "+f"(acc[n][2]), "+f"(acc[n][3])
                             : "r"(al0), "r"(al1), "r"(al2), "r"(al3), "r"(bh0), "r"(bh1));
                asm volatile("mma.sync.aligned.m16n8k16.row.col.f32.bf16.bf16.f32 "
                             "{%0,%1,%2,%3},{%4,%5,%6,%7},{%8,%9},{%0,%1,%2,%3};"
                             : "+f"(acc[n][0]), "+f"(acc[n][1]), "+f"(acc[n][2]), "+f"(acc[n][3])
                             : "r"(ah0), "r"(ah1), "r"(ah2), "r"(ah3), "r"(bl0), "r"(bl1));
            }
        }
        __syncthreads();
    }

    // ---- epilogue ----
    int gr0 = r0 + wid * 16 + (lane >> 2);
    int gr1 = gr0 + 8;
#pragma unroll
    for (int n = 0; n < NT; n++) {
        int col = col0 + n * 8 + (lane & 3) * 2;
        float v0 = acc[n][0], v1 = acc[n][1], v2 = acc[n][2], v3 = acc[n][3];
        if (EPI >= 1) {
            float b0 = bias[col], b1 = bias[col + 1];
            v0 += b0; v1 += b1; v2 += b0; v3 += b1;
            if (EPI == 1) {
                v0 = fmaxf(v0, 0.f); v1 = fmaxf(v1, 0.f);
                v2 = fmaxf(v2, 0.f); v3 = fmaxf(v3, 0.f);
            }
        }
        if (gr0 < nrows) *(float2*)&Y[(size_t)gr0 * ldy + col] = make_float2(v0, v1);
        if (gr1 < nrows) *(float2*)&Y[(size_t)gr1 * ldy + col] = make_float2(v2, v3);
    }
}

// ---------------- per-graph max pool (sequential, no atomics) ------------
__global__ void pool_kernel(const float* __restrict__ H) {
    int g = blockIdx.x;
    int c = threadIdx.x;   // 128
    int s = g_gptr[g], e = g_gptr[g + 1];
    float m = 0.f;         // post-relu >= 0; empty graph -> 0
    for (int i = s; i < e; i++)
        m = fmaxf(m, H[(size_t)i * 128 + c]);
    g_pool[g * 128 + c] = m;
}

// ---------------- CSR gather (vectorized): O = P @ H ---------------------
template<int C, bool EPI>
__global__ __launch_bounds__(256)
void gather_kernel(const float* __restrict__ H, float* __restrict__ O,
                   const float* __restrict__ bias) {
    constexpr int L = C / 4;
    int idx = blockIdx.x * 256 + threadIdx.x;
    int node = idx / L;
    int c4 = (idx % L) * 4;
    if (node >= NN) return;
    int s = g_rowptr[node], e = g_rowptr[node + 1];
    float ax = 0.f, ay = 0.f, az = 0.f, aw = 0.f;
    for (int k = s; k < e; k++) {
        float2 ew = g_csr2[k];
        int src = __float_as_int(ew.x);
        float w = ew.y;
        float4 h = *(const float4*)&H[(size_t)src * C + c4];
        ax += h.x * w; ay += h.y * w; az += h.z * w; aw += h.w * w;
    }
    float d = g_dis[node];
    float d2 = d * d;
    float4 hn = *(const float4*)&H[(size_t)node * C + c4];
    float4 o;
    o.x = d * ax + hn.x * d2;
    o.y = d * ay + hn.y * d2;
    o.z = d * az + hn.z * d2;
    o.w = d * aw + hn.w * d2;
    if (EPI) {
        float4 b = *(const float4*)&bias[c4];
        o.x = fmaxf(o.x + b.x, 0.f);
        o.y = fmaxf(o.y + b.y, 0.f);
        o.z = fmaxf(o.z + b.z, 0.f);
        o.w = fmaxf(o.w + b.w, 0.f);
    }
    *(float4*)&O[(size_t)node * C + c4] = o;
}

// ---------------- launch ----------------
extern "C" void kernel_launch(void* const* d_in, const int* in_sizes, int n_in,
                              void* d_out, int out_size) {
    const float* x     = (const float*)d_in[0];
    const void*  ei    = d_in[1];
    const void*  batch = d_in[2];
    const float* nw    = (const float*)d_in[3];
    const float* nbi   = (const float*)d_in[4];
    const float* W1    = (const float*)d_in[5];
    const float* b1    = (const float*)d_in[6];
    const float* W2    = (const float*)d_in[7];
    const float* b2    = (const float*)d_in[8];
    const float* W3    = (const float*)d_in[9];
    const float* b3    = (const float*)d_in[10];
    const float* l1W   = (const float*)d_in[11];
    const float* l1b   = (const float*)d_in[12];
    const float* l2W   = (const float*)d_in[13];
    const float* l2b   = (const float*)d_in[14];
    float* out = (float*)d_out;

    void *pA, *pB, *pC, *pPool;
    cudaGetSymbolAddress(&pA, g_bufA);
    cudaGetSymbolAddress(&pB, g_bufB);
    cudaGetSymbolAddress(&pC, g_bufC);
    cudaGetSymbolAddress(&pPool, g_pool);
    float* fA = (float*)pA;
    float* fB = (float*)pB;
    float* fC = (float*)pC;
    const float* poolf = (const float*)pPool;

    const int NB_SCAN = (NN + SCAN_B - 1) / SCAN_B;

    detect_kernel<<<1, 32>>>(ei, batch);
    init_kernel<<<(NN + 255) / 256, 256>>>();
    batchinfo_kernel<<<(NN + 255) / 256, 256>>>(batch);
    count_kernel<<<(EE + 255) / 256, 256>>>(ei);

    scan1_kernel<<<NB_SCAN, SCAN_B>>>();
    scan2_kernel<<<1, SCAN_B>>>(NB_SCAN);
    scan3_kernel<<<(NN + 255) / 256, 256>>>();
    fill_kernel<<<(EE + 255) / 256, 256>>>(ei);

    stats_kernel<<<GG, 128>>>(x, nw, nbi);

    const int GB = (NN + 127) / 128;

    // layer 1: (norm ∘ x) @ W1 -> B(32ch); propagate w/ bias+relu -> A
    mma_gemm<128, 32, true, 0><<<GB, 256>>>(x, W1, 32, nullptr, fB, 32, NN);
    gather_kernel<32, true><<<(NN * 8 + 255) / 256, 256>>>(fB, fA, b1);

    // layer 2: propagate (32ch) -> C; GEMM 32->64 w/ bias+relu -> B
    gather_kernel<32, false><<<(NN * 8 + 255) / 256, 256>>>(fA, fC, nullptr);
    mma_gemm<32, 64, false, 1><<<GB, 256>>>(fC, W2, 64, b2, fB, 64, NN);

    // layer 3: propagate (64ch) -> A; GEMM 64->128 w/ bias+relu -> C; pool
    gather_kernel<64, false><<<(NN * 16 + 255) / 256, 256>>>(fB, fA, nullptr);
    mma_gemm<64, 128, false, 1><<<GB, 256>>>(fA, W3, 128, b3, fC, 128, NN);
    pool_kernel<<<GG, 128>>>(fC);

    // head: pooled[G,128] @ l1W (+relu) -> B[G,256]; @ l2W (+bias) -> out
    {
        dim3 grid1((GG + 127) / 128, 4);
        mma_gemm<128, 64, false, 1><<<grid1, 256>>>(poolf, l1W, 256, l1b, fB, 256, GG);
        dim3 grid2((GG + 127) / 128, 2);
        mma_gemm<256, 64, false, 3><<<grid2, 256>>>(fB, l2W, 128, l2b, out, 128, GG);
    }
}

// round 7
// speedup vs baseline: 2.7528x; 1.0613x over previous
#include <cuda_runtime.h>
#include <cuda_bf16.h>
#include <cstdint>
#include <cstddef>

#define NN   200000
#define EE   800000
#define FIN  128
#define GG   8000
#define SCAN_B 512

// ---------------- device scratch ----------------
__device__ float g_bufA[(size_t)NN * 128];
__device__ float g_bufB[(size_t)NN * 128];
__device__ float g_bufC[(size_t)NN * 128];
__device__ float g_dis[NN];
__device__ int   g_cnt[NN];
__device__ int   g_rowptr[NN + 1];
__device__ int   g_fill[NN];
__device__ float2 g_csr2[EE];          // packed {src_bits, dis[src]}
__device__ int   g_bsum[SCAN_B];
__device__ int   g_boff[SCAN_B];
__device__ int   g_gptr[GG + 1];
__device__ int   g_nodeg[NN];
__device__ float g_na[GG * 128];
__device__ float g_nb[GG * 128];
__device__ int   g_pool[GG * 128];     // float bits; post-relu >= 0 so int max == float max
__device__ int   g_ei64;
__device__ int   g_b64;

__device__ __forceinline__ long long ld_idx(const void* p, long long i, int is64) {
    if (is64) return ((const long long*)p)[i];
    return (long long)((const int*)p)[i];
}

// ---------------- dtype width detection (warp-parallel) ----------------
__global__ void detect_kernel(const void* ei, const void* batch) {
    int lane = threadIdx.x;
    long long v = ((const long long*)ei)[lane];
    unsigned bad1 = __ballot_sync(0xffffffffu, v < 0 || v >= NN);
    long long q = ((const long long*)batch)[lane];
    unsigned bad2 = __ballot_sync(0xffffffffu, q < 0 || q >= GG);
    if (lane == 0) {
        g_ei64 = (bad1 == 0u);
        g_b64  = (bad2 == 0u);
    }
}

// ---------------- init (cnt + pool) ----------------
__global__ void init_kernel() {
    int i = blockIdx.x * blockDim.x + threadIdx.x;
    if (i < NN) g_cnt[i] = 0;
    if (i < GG * 128) g_pool[i] = 0;
}

// nodeg + graph boundary pointers (batch sorted)
__global__ void batchinfo_kernel(const void* __restrict__ batch) {
    int i = blockIdx.x * blockDim.x + threadIdx.x;
    if (i >= NN) return;
    int is64 = g_b64;
    int bi = (int)ld_idx(batch, i, is64);
    g_nodeg[i] = bi;
    if (i == 0) {
        for (int g = 0; g <= bi; g++) g_gptr[g] = 0;
    } else {
        int bp = (int)ld_idx(batch, i - 1, is64);
        for (int g = bp + 1; g <= bi; g++) g_gptr[g] = i;
    }
    if (i == NN - 1) {
        for (int g = bi + 1; g <= GG; g++) g_gptr[g] = NN;
    }
}

// ---------------- degree ----------------
__global__ void count_kernel(const void* __restrict__ ei) {
    int i = blockIdx.x * blockDim.x + threadIdx.x;
    if (i >= EE) return;
    int dst = (int)ld_idx(ei, (long long)EE + i, g_ei64);
    atomicAdd(&g_cnt[dst], 1);
}

// ---------------- exclusive scan of g_cnt -> g_rowptr (+ dis fused) ------
__global__ void scan1_kernel() {
    __shared__ int s[SCAN_B];
    int tid = threadIdx.x;
    int i = blockIdx.x * SCAN_B + tid;
    int v = (i < NN) ? g_cnt[i] : 0;
    if (i < NN) g_dis[i] = rsqrtf(1.0f + (float)v);
    s[tid] = v;
    __syncthreads();
    for (int off = 1; off < SCAN_B; off <<= 1) {
        int t = (tid >= off) ? s[tid - off] : 0;
        __syncthreads();
        s[tid] += t;
        __syncthreads();
    }
    if (i < NN) g_rowptr[i] = s[tid] - v;
    if (tid == SCAN_B - 1) g_bsum[blockIdx.x] = s[tid];
}
__global__ void scan2_kernel(int nb) {
    __shared__ int s[SCAN_B];
    int tid = threadIdx.x;
    int v = (tid < nb) ? g_bsum[tid] : 0;
    s[tid] = v;
    __syncthreads();
    for (int off = 1; off < SCAN_B; off <<= 1) {
        int t = (tid >= off) ? s[tid - off] : 0;
        __syncthreads();
        s[tid] += t;
        __syncthreads();
    }
    g_boff[tid] = s[tid] - v;
}
__global__ void scan3_kernel() {
    int i = blockIdx.x * blockDim.x + threadIdx.x;
    if (i < NN) {
        int v = g_rowptr[i] + g_boff[i / SCAN_B];
        g_rowptr[i] = v;
        g_fill[i] = v;
    }
    if (i == 0) g_rowptr[NN] = EE;
}

// ---------------- CSR fill (packed) ----------------
__global__ void fill_kernel(const void* __restrict__ ei) {
    int i = blockIdx.x * blockDim.x + threadIdx.x;
    if (i >= EE) return;
    int is64 = g_ei64;
    int src = (int)ld_idx(ei, i, is64);
    int dst = (int)ld_idx(ei, (long long)EE + i, is64);
    int pos = atomicAdd(&g_fill[dst], 1);
    g_csr2[pos] = make_float2(__int_as_float(src), g_dis[src]);
}

// ---------------- instance norm stats -> affine (v*na + nb) --------------
__global__ void stats_kernel(const float* __restrict__ x,
                             const float* __restrict__ wp,
                             const float* __restrict__ bp) {
    int g = blockIdx.x;
    int c = threadIdx.x;   // 128
    int s = g_gptr[g], e = g_gptr[g + 1];
    if (s >= e) { g_na[g * 128 + c] = 0.f; g_nb[g * 128 + c] = 0.f; return; }
    float w = wp[0], b = bp[0];
    float sum = 0.f, sq = 0.f;
    for (int i = s; i < e; i++) {
        float v = x[(size_t)i * FIN + c];
        sum += v; sq += v * v;
    }
    float cnt  = (float)(e - s);
    float mean = sum / cnt;
    float var  = sq / cnt - mean * mean;
    float inv  = rsqrtf(var + 1e-5f);
    float na = inv * w;
    g_na[g * 128 + c] = na;
    g_nb[g * 128 + c] = b - mean * na;
}

// ---------------- bf16x3 split tensor-core GEMM --------------------------
// Y[r, col0+c] = sum_k X[r,k] * W[k, col0+c]   (only lo*lo dropped)
// 256 threads / 8 warps, 128 rows per block; warp w -> rows [w*16, w*16+16).
// EPI: 0 plain, 1 bias+relu, 2 bias+relu + fused per-graph max-pool (NO Y),
//      3 bias only.  NORM: fuse instnorm affine (CIN must be 128).
template<int CIN, int COUT, bool NORM, int EPI>
__global__ __launch_bounds__(256)
void mma_gemm(const float* __restrict__ X, const float* __restrict__ W,
              int ldw, const float* __restrict__ bias,
              float* __restrict__ Y, int ldy, int nrows) {
    constexpr int KCH = 32;
    constexpr int ST  = 40;              // padded stride (bf16), 80B rows
    constexpr int NT  = COUT / 8;        // n-tiles (even)
    constexpr int PSLOT = (EPI == 2) ? 32 : 1;

    __shared__ __align__(16) __nv_bfloat16 sXhi[128 * ST];
    __shared__ __align__(16) __nv_bfloat16 sXlo[128 * ST];
    __shared__ __align__(16) __nv_bfloat16 sWhi[COUT * ST];
    __shared__ __align__(16) __nv_bfloat16 sWlo[COUT * ST];
    __shared__ int sPool[PSLOT * 128];

    int tid = threadIdx.x;
    int wid = tid >> 5;
    int lane = tid & 31;
    int r0 = blockIdx.x * 128;
    int col0 = blockIdx.y * COUT;

    if (EPI == 2) {
        for (int i = tid; i < PSLOT * 128; i += 256) sPool[i] = 0;
    }

    float acc[NT][4];
#pragma unroll
    for (int n = 0; n < NT; n++)
#pragma unroll
        for (int j = 0; j < 4; j++) acc[n][j] = 0.f;

    // ldmatrix base addresses
    int arow = lane & 15;
    int akoff = (lane >> 4) * 8;
    unsigned aAhi = (unsigned)__cvta_generic_to_shared(
        &sXhi[(wid * 16 + arow) * ST + akoff]);
    unsigned aAlo = (unsigned)__cvta_generic_to_shared(
        &sXlo[(wid * 16 + arow) * ST + akoff]);
    // B paired x4: m0 = tile n (k0), m1 = tile n (k8), m2 = tile n+1 (k0), m3 = tile n+1 (k8)
    int brow = (lane & 7) + (lane >> 4) * 8;     // +8 rows for lanes 16..31 (next tile)
    int bkoff = ((lane >> 3) & 1) * 8;
    unsigned aBhi = (unsigned)__cvta_generic_to_shared(&sWhi[brow * ST + bkoff]);
    unsigned aBlo = (unsigned)__cvta_generic_to_shared(&sWlo[brow * ST + bkoff]);

    for (int k0 = 0; k0 < CIN; k0 += KCH) {
        // ---- X chunk: fp32 -> hi/lo bf16, vectorized bf162 stores ----
        for (int i = tid; i < 128 * (KCH / 4); i += 256) {
            int rl = i / (KCH / 4);
            int kq = i % (KCH / 4);
            int row = r0 + rl;
            float4 v = make_float4(0.f, 0.f, 0.f, 0.f);
            if (row < nrows) {
                v = *(const float4*)&X[(size_t)row * CIN + k0 + kq * 4];
                if (NORM) {
                    int g = g_nodeg[row];
                    const float4 na = *(const float4*)&g_na[g * 128 + k0 + kq * 4];
                    const float4 nb = *(const float4*)&g_nb[g * 128 + k0 + kq * 4];
                    v.x = v.x * na.x + nb.x; v.y = v.y * na.y + nb.y;
                    v.z = v.z * na.z + nb.z; v.w = v.w * na.w + nb.w;
                }
            }
            __nv_bfloat162 h01 = __floats2bfloat162_rn(v.x, v.y);
            __nv_bfloat162 h23 = __floats2bfloat162_rn(v.z, v.w);
            __nv_bfloat162 l01 = __floats2bfloat162_rn(
                v.x - __bfloat162float(h01.x), v.y - __bfloat162float(h01.y));
            __nv_bfloat162 l23 = __floats2bfloat162_rn(
                v.z - __bfloat162float(h23.x), v.w - __bfloat162float(h23.y));
            int base = rl * ST + kq * 4;        // byte off = rl*80 + kq*8 (8B aligned)
            uint2 hu, lu;
            hu.x = *(unsigned*)&h01; hu.y = *(unsigned*)&h23;
            lu.x = *(unsigned*)&l01; lu.y = *(unsigned*)&l23;
            *(uint2*)&sXhi[base] = hu;
            *(uint2*)&sXlo[base] = lu;
        }
        // ---- W chunk: [k][c] -> Wt [c][k], coalesced loads, bf162 stores ----
        for (int i = tid; i < COUT * (KCH / 2); i += 256) {
            int c  = i % COUT;
            int kp = i / COUT;
            int k  = kp * 2;
            float w0 = W[(size_t)(k0 + k)     * ldw + col0 + c];
            float w1 = W[(size_t)(k0 + k + 1) * ldw + col0 + c];
            __nv_bfloat162 h = __floats2bfloat162_rn(w0, w1);
            __nv_bfloat162 l = __floats2bfloat162_rn(
                w0 - __bfloat162float(h.x), w1 - __bfloat162float(h.y));
            *(__nv_bfloat162*)&sWhi[c * ST + k] = h;
            *(__nv_bfloat162*)&sWlo[c * ST + k] = l;
        }
        __syncthreads();

#pragma unroll
        for (int ks = 0; ks < KCH / 16; ks++) {
            unsigned ah0, ah1, ah2, ah3, al0, al1, al2, al3;
            asm volatile("ldmatrix.sync.aligned.m8n8.x4.shared.b16 {%0,%1,%2,%3}, [%4];"
                         : "=r"(ah0), "=r"(ah1), "=r"(ah2), "=r"(ah3)
                         : "r"(aAhi + ks * 32u));
            asm volatile("ldmatrix.sync.aligned.m8n8.x4.shared.b16 {%0,%1,%2,%3}, [%4];"
                         : "=r"(al0), "=r"(al1), "=r"(al2), "=r"(al3)
                         : "r"(aAlo + ks * 32u));
#pragma unroll
            for (int np = 0; np < NT / 2; np++) {
                unsigned bh0, bh1, bh2, bh3, bl0, bl1, bl2, bl3;
                unsigned boff = (unsigned)(np * 16 * ST * 2) + ks * 32u;
                asm volatile("ldmatrix.sync.aligned.m8n8.x4.shared.b16 {%0,%1,%2,%3}, [%4];"
                             : "=r"(bh0), "=r"(bh1), "=r"(bh2), "=r"(bh3)
                             : "r"(aBhi + boff));
                asm volatile("ldmatrix.sync.aligned.m8n8.x4.shared.b16 {%0,%1,%2,%3}, [%4];"
                             : "=r"(bl0), "=r"(bl1), "=r"(bl2), "=r"(bl3)
                             : "r"(aBlo + boff));
                int n0 = np * 2, n1 = np * 2 + 1;
                asm volatile("mma.sync.aligned.m16n8k16.row.col.f32.bf16.bf16.f32 "
                             "{%0,%1,%2,%3},{%4,%5,%6,%7},{%8,%9},{%0,%1,%2,%3};"
                             : "+f"(acc[n0][0]), "+f"(acc[n0][1]), "+f"(acc[n0][2]), "+f"(acc[n0][3])
                             : "r"(ah0), "r"(ah1), "r"(ah2), "r"(ah3), "r"(bh0), "r"(bh1));
                asm volatile("mma.sync.aligned.m16n8k16.row.col.f32.bf16.bf16.f32 "
                             "{%0,%1,%2,%3},{%4,%5,%6,%7},{%8,%9},{%0,%1,%2,%3};"
                             : "+f"(acc[n0][0]), "+f"(acc[n0][1]), "+f"(acc[n0][2]), "+f"(acc[n0][3])
                             : "r"(al0), "r"(al1), "r"(al2), "r"(al3), "r"(bh0), "r"(bh1));
                asm volatile("mma.sync.aligned.m16n8k16.row.col.f32.bf16.bf16.f32 "
                             "{%0,%1,%2,%3},{%4,%5,%6,%7},{%8,%9},{%0,%1,%2,%3};"
                             : "+f"(acc[n0][0]), "+f"(acc[n0][1]), "+f"(acc[n0][2]), "+f"(acc[n0][3])
                             : "r"(ah0), "r"(ah1), "r"(ah2), "r"(ah3), "r"(bl0), "r"(bl1));
                asm volatile("mma.sync.aligned.m16n8k16.row.col.f32.bf16.bf16.f32 "
                             "{%0,%1,%2,%3},{%4,%5,%6,%7},{%8,%9},{%0,%1,%2,%3};"
                             : "+f"(acc[n1][0]), "+f"(acc[n1][1]), "+f"(acc[n1][2]), "+f"(acc[n1][3])
                             : "r"(ah0), "r"(ah1), "r"(ah2), "r"(ah3), "r"(bh2), "r"(bh3));
                asm volatile("mma.sync.aligned.m16n8k16.row.col.f32.bf16.bf16.f32 "
                             "{%0,%1,%2,%3},{%4,%5,%6,%7},{%8,%9},{%0,%1,%2,%3};"
                             : "+f"(acc[n1][0]), "+f"(acc[n1][1]), "+f"(acc[n1][2]), "+f"(acc[n1][3])
                             : "r"(al0), "r"(al1), "r"(al2), "r"(al3), "r"(bh2), "r"(bh3));
                asm volatile("mma.sync.aligned.m16n8k16.row.col.f32.bf16.bf16.f32 "
                             "{%0,%1,%2,%3},{%4,%5,%6,%7},{%8,%9},{%0,%1,%2,%3};"
                             : "+f"(acc[n1][0]), "+f"(acc[n1][1]), "+f"(acc[n1][2]), "+f"(acc[n1][3])
                             : "r"(ah0), "r"(ah1), "r"(ah2), "r"(ah3), "r"(bl2), "r"(bl3));
            }
        }
        __syncthreads();
    }

    // ---- epilogue ----
    int gr0 = r0 + wid * 16 + (lane >> 2);
    int gr1 = gr0 + 8;

    if (EPI == 2) {
        int gmin = g_nodeg[r0];
        int glast = g_nodeg[min(r0 + 127, nrows - 1)];
        int g0 = (gr0 < nrows) ? g_nodeg[gr0] : -1;
        int g1 = (gr1 < nrows) ? g_nodeg[gr1] : -1;
        int i0 = g0 - gmin, i1 = g1 - gmin;
#pragma unroll
        for (int n = 0; n < NT; n++) {
            int col = col0 + n * 8 + (lane & 3) * 2;
            float b0 = bias[col], b1 = bias[col + 1];
            float v0 = fmaxf(acc[n][0] + b0, 0.f);
            float v1 = fmaxf(acc[n][1] + b1, 0.f);
            float v2 = fmaxf(acc[n][2] + b0, 0.f);
            float v3 = fmaxf(acc[n][3] + b1, 0.f);
            if (g0 >= 0) {
                if ((unsigned)i0 < 32u) {
                    atomicMax(&sPool[i0 * 128 + col],     __float_as_int(v0));
                    atomicMax(&sPool[i0 * 128 + col + 1], __float_as_int(v1));
                } else {
                    atomicMax(&g_pool[g0 * 128 + col],     __float_as_int(v0));
                    atomicMax(&g_pool[g0 * 128 + col + 1], __float_as_int(v1));
                }
            }
            if (g1 >= 0) {
                if ((unsigned)i1 < 32u) {
                    atomicMax(&sPool[i1 * 128 + col],     __float_as_int(v2));
                    atomicMax(&sPool[i1 * 128 + col + 1], __float_as_int(v3));
                } else {
                    atomicMax(&g_pool[g1 * 128 + col],     __float_as_int(v2));
                    atomicMax(&g_pool[g1 * 128 + col + 1], __float_as_int(v3));
                }
            }
        }
        __syncthreads();
        int span = min(glast - gmin, 31);
        int total = (span + 1) * 128;
        for (int i = tid; i < total; i += 256) {
            int b = sPool[i];
            if (b != 0)
                atomicMax(&g_pool[(gmin + i / 128) * 128 + (i & 127)], b);
        }
    } else {
#pragma unroll
        for (int n = 0; n < NT; n++) {
            int col = col0 + n * 8 + (lane & 3) * 2;
            float v0 = acc[n][0], v1 = acc[n][1], v2 = acc[n][2], v3 = acc[n][3];
            if (EPI >= 1) {
                float b0 = bias[col], b1 = bias[col + 1];
                v0 += b0; v1 += b1; v2 += b0; v3 += b1;
                if (EPI == 1) {
                    v0 = fmaxf(v0, 0.f); v1 = fmaxf(v1, 0.f);
                    v2 = fmaxf(v2, 0.f); v3 = fmaxf(v3, 0.f);
                }
            }
            if (gr0 < nrows) *(float2*)&Y[(size_t)gr0 * ldy + col] = make_float2(v0, v1);
            if (gr1 < nrows) *(float2*)&Y[(size_t)gr1 * ldy + col] = make_float2(v2, v3);
        }
    }
}

// ---------------- CSR gather (vectorized): O = P @ H ---------------------
template<int C, bool EPI>
__global__ __launch_bounds__(256)
void gather_kernel(const float* __restrict__ H, float* __restrict__ O,
                   const float* __restrict__ bias) {
    constexpr int L = C / 4;
    int idx = blockIdx.x * 256 + threadIdx.x;
    int node = idx / L;
    int c4 = (idx % L) * 4;
    if (node >= NN) return;
    int s = g_rowptr[node], e = g_rowptr[node + 1];
    float ax = 0.f, ay = 0.f, az = 0.f, aw = 0.f;
    for (int k = s; k < e; k++) {
        float2 ew = g_csr2[k];
        int src = __float_as_int(ew.x);
        float w = ew.y;
        float4 h = *(const float4*)&H[(size_t)src * C + c4];
        ax += h.x * w; ay += h.y * w; az += h.z * w; aw += h.w * w;
    }
    float d = g_dis[node];
    float d2 = d * d;
    float4 hn = *(const float4*)&H[(size_t)node * C + c4];
    float4 o;
    o.x = d * ax + hn.x * d2;
    o.y = d * ay + hn.y * d2;
    o.z = d * az + hn.z * d2;
    o.w = d * aw + hn.w * d2;
    if (EPI) {
        float4 b = *(const float4*)&bias[c4];
        o.x = fmaxf(o.x + b.x, 0.f);
        o.y = fmaxf(o.y + b.y, 0.f);
        o.z = fmaxf(o.z + b.z, 0.f);
        o.w = fmaxf(o.w + b.w, 0.f);
    }
    *(float4*)&O[(size_t)node * C + c4] = o;
}

// ---------------- launch ----------------
extern "C" void kernel_launch(void* const* d_in, const int* in_sizes, int n_in,
                              void* d_out, int out_size) {
    const float* x     = (const float*)d_in[0];
    const void*  ei    = d_in[1];
    const void*  batch = d_in[2];
    const float* nw    = (const float*)d_in[3];
    const float* nbi   = (const float*)d_in[4];
    const float* W1    = (const float*)d_in[5];
    const float* b1    = (const float*)d_in[6];
    const float* W2    = (const float*)d_in[7];
    const float* b2    = (const float*)d_in[8];
    const float* W3    = (const float*)d_in[9];
    const float* b3    = (const float*)d_in[10];
    const float* l1W   = (const float*)d_in[11];
    const float* l1b   = (const float*)d_in[12];
    const float* l2W   = (const float*)d_in[13];
    const float* l2b   = (const float*)d_in[14];
    float* out = (float*)d_out;

    void *pA, *pB, *pC, *pPool;
    cudaGetSymbolAddress(&pA, g_bufA);
    cudaGetSymbolAddress(&pB, g_bufB);
    cudaGetSymbolAddress(&pC, g_bufC);
    cudaGetSymbolAddress(&pPool, g_pool);
    float* fA = (float*)pA;
    float* fB = (float*)pB;
    float* fC = (float*)pC;
    const float* poolf = (const float*)pPool;   // bit-pattern of >=0 floats

    const int NB_SCAN = (NN + SCAN_B - 1) / SCAN_B;

    detect_kernel<<<1, 32>>>(ei, batch);
    init_kernel<<<(GG * 128 + 255) / 256, 256>>>();
    batchinfo_kernel<<<(NN + 255) / 256, 256>>>(batch);
    count_kernel<<<(EE + 255) / 256, 256>>>(ei);

    scan1_kernel<<<NB_SCAN, SCAN_B>>>();
    scan2_kernel<<<1, SCAN_B>>>(NB_SCAN);
    scan3_kernel<<<(NN + 255) / 256, 256>>>();
    fill_kernel<<<(EE + 255) / 256, 256>>>(ei);

    stats_kernel<<<GG, 128>>>(x, nw, nbi);

    const int GB = (NN + 127) / 128;

    // layer 1: (norm ∘ x) @ W1 -> B(32ch); propagate w/ bias+relu -> A
    mma_gemm<128, 32, true, 0><<<GB, 256>>>(x, W1, 32, nullptr, fB, 32, NN);
    gather_kernel<32, true><<<(NN * 8 + 255) / 256, 256>>>(fB, fA, b1);

    // layer 2: propagate (32ch) -> C; GEMM 32->64 w/ bias+relu -> B
    gather_kernel<32, false><<<(NN * 8 + 255) / 256, 256>>>(fA, fC, nullptr);
    mma_gemm<32, 64, false, 1><<<GB, 256>>>(fC, W2, 64, b2, fB, 64, NN);

    // layer 3: propagate (64ch) -> A; GEMM 64->128 + bias+relu + FUSED pool
    gather_kernel<64, false><<<(NN * 16 + 255) / 256, 256>>>(fB, fA, nullptr);
    mma_gemm<64, 128, false, 2><<<GB, 256>>>(fA, W3, 128, b3, nullptr, 128, NN);

    // head: pooled[G,128] @ l1W (+relu) -> B[G,256]; @ l2W (+bias) -> out
    {
        dim3 grid1((GG + 127) / 128, 4);
        mma_gemm<128, 64, false, 1><<<grid1, 256>>>(poolf, l1W, 256, l1b, fB, 256, GG);
        dim3 grid2((GG + 127) / 128, 2);
        mma_gemm<256, 64, false, 3><<<grid2, 256>>>(fB, l2W, 128, l2b, out, 128, GG);
    }
}